// round 1
// baseline (speedup 1.0000x reference)
#include <cuda_runtime.h>
#include <cuda_bf16.h>
#include <math.h>

// Problem constants
#define BSZ 4
#define SEQ 2048
#define DMODEL 1024
#define NHEADS 16
#define DHEAD 64
#define QKVCOLS (3 * DMODEL)          // 3072
#define MROWS (BSZ * SEQ)             // 8192

// Scratch (device globals: the only sanctioned scratch mechanism)
__device__ float g_qkv[(size_t)MROWS * QKVCOLS];      // 8192 x 3072
__device__ float g_attn[(size_t)MROWS * DMODEL];      // 8192 x 1024

// ---------------------------------------------------------------------------
// Tiled fp32 GEMM: C[M,N] = A[M,K] * B[K,N]   (row-major, M,N,K multiples of 64/16)
// BM=BN=64, BK=16, 256 threads, 4x4 micro-tile per thread.
// ---------------------------------------------------------------------------
__global__ __launch_bounds__(256) void gemm_kernel(
    const float* __restrict__ A, const float* __restrict__ B,
    float* __restrict__ C, int M, int N, int K)
{
    __shared__ float As[16][64];   // As[k][m]
    __shared__ float Bs[16][64];   // Bs[k][n]

    const int tid = threadIdx.x;
    const int tx = tid % 16;       // column group
    const int ty = tid / 16;       // row group
    const int rowBase = blockIdx.y * 64;
    const int colBase = blockIdx.x * 64;

    // A-load mapping: one float4 per thread along K
    const int a_m  = tid / 4;            // 0..63
    const int a_k4 = (tid % 4) * 4;      // 0,4,8,12
    // B-load mapping: one float4 per thread along N
    const int b_k  = tid / 16;           // 0..15
    const int b_n4 = (tid % 16) * 4;     // 0..60

    float acc[4][4];
#pragma unroll
    for (int a = 0; a < 4; ++a)
#pragma unroll
        for (int bb = 0; bb < 4; ++bb) acc[a][bb] = 0.0f;

    for (int k0 = 0; k0 < K; k0 += 16) {
        // Load A tile (64x16) -> As[k][m]
        float4 av = *reinterpret_cast<const float4*>(
            &A[(size_t)(rowBase + a_m) * K + k0 + a_k4]);
        As[a_k4 + 0][a_m] = av.x;
        As[a_k4 + 1][a_m] = av.y;
        As[a_k4 + 2][a_m] = av.z;
        As[a_k4 + 3][a_m] = av.w;
        // Load B tile (16x64) -> Bs[k][n]
        float4 bv = *reinterpret_cast<const float4*>(
            &B[(size_t)(k0 + b_k) * N + colBase + b_n4]);
        *reinterpret_cast<float4*>(&Bs[b_k][b_n4]) = bv;
        __syncthreads();

#pragma unroll
        for (int k = 0; k < 16; ++k) {
            float ra[4], rb[4];
#pragma unroll
            for (int a = 0; a < 4; ++a) ra[a] = As[k][ty * 4 + a];
#pragma unroll
            for (int bb = 0; bb < 4; ++bb) rb[bb] = Bs[k][tx * 4 + bb];
#pragma unroll
            for (int a = 0; a < 4; ++a)
#pragma unroll
                for (int bb = 0; bb < 4; ++bb)
                    acc[a][bb] = fmaf(ra[a], rb[bb], acc[a][bb]);
        }
        __syncthreads();
    }

#pragma unroll
    for (int a = 0; a < 4; ++a) {
        float4 v = make_float4(acc[a][0], acc[a][1], acc[a][2], acc[a][3]);
        *reinterpret_cast<float4*>(
            &C[(size_t)(rowBase + ty * 4 + a) * N + colBase + tx * 4]) = v;
    }
}

// ---------------------------------------------------------------------------
// Causal flash attention. One CTA per (q-tile, head, batch).
// 64 threads; each thread owns one query row. Online softmax, fp32.
// Q stored transposed in SMEM (conflict-free per-thread reads),
// K/V rows read broadcast. SMEM = 3 * 16KB = 48KB exactly (static limit).
// ---------------------------------------------------------------------------
__global__ __launch_bounds__(64) void attn_kernel(
    const float* __restrict__ qkv, float* __restrict__ out)
{
    __shared__ float Qs[DHEAD][64];   // Qs[i][row]
    __shared__ float Ks[64][DHEAD];   // Ks[j][i]
    __shared__ float Vs[64][DHEAD];   // Vs[j][i]

    const int tid = threadIdx.x;           // query row within tile
    const int rt  = blockIdx.x;            // q tile (0..31)
    const int h   = blockIdx.y;            // head
    const int b   = blockIdx.z;            // batch

    const size_t rowStride = QKVCOLS;
    const float* qbase = qkv + ((size_t)b * SEQ + (size_t)rt * 64) * rowStride + h * DHEAD;

    // Load Q tile transposed: thread tid owns query row tid
#pragma unroll 8
    for (int i = 0; i < DHEAD; ++i)
        Qs[i][tid] = qbase[(size_t)tid * rowStride + i];

    float o[DHEAD];
#pragma unroll
    for (int i = 0; i < DHEAD; ++i) o[i] = 0.0f;
    float m = -INFINITY, l = 0.0f;

    const int q_row = rt * 64 + tid;
    const float scale = 0.125f;  // 1/sqrt(64)

    for (int kt = 0; kt <= rt; ++kt) {
        const float* kbase = qkv + ((size_t)b * SEQ + (size_t)kt * 64) * rowStride
                                 + DMODEL + h * DHEAD;
        __syncthreads();
        for (int r = 0; r < 64; ++r) {
            Ks[r][tid] = kbase[(size_t)r * rowStride + tid];
            Vs[r][tid] = kbase[(size_t)r * rowStride + DMODEL + tid];
        }
        __syncthreads();

        const bool masked_tile = (kt == rt);
        for (int j = 0; j < 64; ++j) {
            float s = 0.0f;
#pragma unroll
            for (int i = 0; i < DHEAD; ++i)
                s = fmaf(Qs[i][tid], Ks[j][i], s);
            s *= scale;
            if (masked_tile && (kt * 64 + j) > q_row) s = -INFINITY;

            float mnew = fmaxf(m, s);
            float p    = __expf(s - mnew);
            float corr = __expf(m - mnew);
            l = l * corr + p;
#pragma unroll
            for (int i = 0; i < DHEAD; ++i)
                o[i] = fmaf(o[i], corr, p * Vs[j][i]);
            m = mnew;
        }
    }

    const float inv_l = 1.0f / l;
    float* obase = out + ((size_t)b * SEQ + q_row) * DMODEL + h * DHEAD;
#pragma unroll 8
    for (int i = 0; i < DHEAD; ++i)
        obase[i] = o[i] * inv_l;
}

// ---------------------------------------------------------------------------
extern "C" void kernel_launch(void* const* d_in, const int* in_sizes, int n_in,
                              void* d_out, int out_size)
{
    const float* x     = (const float*)d_in[0];  // [4,2048,1024]
    const float* W_qkv = (const float*)d_in[1];  // [1024,3072]
    const float* W_out = (const float*)d_in[2];  // [1024,1024]
    // d_in[3] = mask (unused; causal handled analytically)
    float* out = (float*)d_out;                  // [4,2048,1024]

    float* qkv;  cudaGetSymbolAddress((void**)&qkv,  g_qkv);
    float* attn; cudaGetSymbolAddress((void**)&attn, g_attn);

    // 1) QKV projection: [8192,1024] @ [1024,3072]
    gemm_kernel<<<dim3(QKVCOLS / 64, MROWS / 64), 256>>>(
        x, W_qkv, qkv, MROWS, QKVCOLS, DMODEL);

    // 2) Causal multi-head attention
    attn_kernel<<<dim3(SEQ / 64, NHEADS, BSZ), 64>>>(qkv, attn);

    // 3) Output projection: [8192,1024] @ [1024,1024]
    gemm_kernel<<<dim3(DMODEL / 64, MROWS / 64), 256>>>(
        attn, W_out, out, MROWS, DMODEL, DMODEL);
}

// round 4
// speedup vs baseline: 1.6116x; 1.6116x over previous
#include <cuda_runtime.h>
#include <cstdint>
#include <math.h>

// Problem constants
#define BSZ 4
#define SEQ 2048
#define DMODEL 1024
#define NHEADS 16
#define DHEAD 64
#define QKVCOLS (3 * DMODEL)          // 3072
#define MROWS (BSZ * SEQ)             // 8192

// Feature gate: tcgen05 only exists in sm_103a/sm_100a feature passes.
#if defined(__CUDA_ARCH__) && (defined(__CUDA_ARCH_FEAT_SM103_ALL) || defined(__CUDA_ARCH_FEAT_SM100_ALL))
#define HAS_TCGEN05 1
#else
#define HAS_TCGEN05 0
#endif

// Scratch (device globals: the only sanctioned scratch mechanism)
__device__ float g_xc   [(size_t)MROWS * DMODEL];     // x rounded to tf32
__device__ float g_qkv  [(size_t)MROWS * QKVCOLS];    // fp32 QKV
__device__ float g_attn [(size_t)MROWS * DMODEL];     // attention out (tf32-rounded)
__device__ float g_wqkvT[(size_t)QKVCOLS * DMODEL];   // W_qkv^T, tf32
__device__ float g_woutT[(size_t)DMODEL * DMODEL];    // W_out^T, tf32

// ---------------------------------------------------------------------------
// Common helpers
// ---------------------------------------------------------------------------
__device__ __forceinline__ float to_tf32(float x) {
    uint32_t u; asm("cvt.rna.tf32.f32 %0, %1;" : "=r"(u) : "f"(x));
    return __uint_as_float(u);
}
__device__ __forceinline__ uint32_t smem_u32(const void* p) {
    uint32_t a;
    asm("{ .reg .u64 t; cvta.to.shared.u64 t, %1; cvt.u32.u64 %0, t; }"
        : "=r"(a) : "l"(p));
    return a;
}

// cp.async (sm_80+, legal in the compute_103 pass)
#define CP_ASYNC16(dst_u32, src_ptr) \
    asm volatile("cp.async.ca.shared.global [%0], [%1], 16;" \
                 :: "r"(dst_u32), "l"(src_ptr) : "memory")
#define CP_COMMIT() asm volatile("cp.async.commit_group;" ::: "memory")
#define CP_WAIT_1() asm volatile("cp.async.wait_group 1;" ::: "memory")
#define CP_WAIT_0() asm volatile("cp.async.wait_group 0;" ::: "memory")

#define GEMM_SMEM 73728

#if HAS_TCGEN05
// ===========================================================================
// tcgen05 helpers (compiled ONLY in sm_103a-feature passes)
// ===========================================================================
#define TCGEN05_ALLOC(smem_addr, nCols) \
    asm volatile("tcgen05.alloc.cta_group::1.sync.aligned.shared::cta.b32 [%0], %1;" \
                 :: "r"((uint32_t)(smem_addr)), "r"((uint32_t)(nCols)) : "memory")
#define TCGEN05_RELINQUISH() \
    asm volatile("tcgen05.relinquish_alloc_permit.cta_group::1.sync.aligned;")
#define TCGEN05_DEALLOC(tmem_addr, nCols) \
    asm volatile("tcgen05.dealloc.cta_group::1.sync.aligned.b32 %0, %1;" \
                 :: "r"(tmem_addr), "r"((uint32_t)(nCols)))
#define TCGEN05_COMMIT(mbar) \
    asm volatile("tcgen05.commit.cta_group::1.mbarrier::arrive::one.shared::cluster.b64 [%0];" \
                 :: "r"((uint32_t)(mbar)) : "memory")
#define TCGEN05_FENCE_AFTER() \
    asm volatile("tcgen05.fence::after_thread_sync;" ::: "memory")
#define TCGEN05_FENCE_BEFORE() \
    asm volatile("tcgen05.fence::before_thread_sync;" ::: "memory")
#define TCGEN05_WAIT_LD() \
    asm volatile("tcgen05.wait::ld.sync.aligned;" ::: "memory")
#define MBARRIER_INIT(mbar, count) \
    asm volatile("mbarrier.init.shared.b64 [%0], %1;" \
                 :: "r"((uint32_t)(mbar)), "r"((uint32_t)(count)) : "memory")
#define FENCE_ASYNC() \
    asm volatile("fence.proxy.async.shared::cta;" ::: "memory")

#define MBARRIER_WAIT_PARITY(mbar_smem_addr, phase_parity) do { \
    uint32_t _mbar = (uint32_t)(mbar_smem_addr); \
    uint32_t _parity = (uint32_t)(phase_parity); \
    uint32_t _done; \
    asm volatile("{\n\t.reg .pred p;\n\t" \
        "mbarrier.try_wait.parity.acquire.cta.shared::cta.b64 p, [%1], %2;\n\t" \
        "selp.b32 %0, 1, 0, p;\n\t}" \
        : "=r"(_done) : "r"(_mbar), "r"(_parity) : "memory"); \
    if (!_done) { \
        asm volatile("{\n\t.reg .pred P1;\n\t" \
            "WAIT_LOOP_%=:\n\t" \
            "mbarrier.try_wait.parity.acquire.cta.shared::cta.b64 P1, [%0], %1, 0x989680;\n\t" \
            "@P1 bra.uni WAIT_DONE_%=;\n\t" \
            "bra.uni WAIT_LOOP_%=;\n\t" \
            "WAIT_DONE_%=:\n\t}" \
            :: "r"(_mbar), "r"(_parity) : "memory"); \
    } \
} while (0)

#define TCGEN05_LD_32X32B_X32(r, tmem_addr) \
    asm volatile("tcgen05.ld.sync.aligned.32x32b.x32.b32 " \
        "{%0, %1, %2, %3, %4, %5, %6, %7, " \
        " %8, %9, %10, %11, %12, %13, %14, %15, " \
        " %16, %17, %18, %19, %20, %21, %22, %23, " \
        " %24, %25, %26, %27, %28, %29, %30, %31}, [%32];" \
        : "=r"((r)[0]),  "=r"((r)[1]),  "=r"((r)[2]),  "=r"((r)[3]), \
          "=r"((r)[4]),  "=r"((r)[5]),  "=r"((r)[6]),  "=r"((r)[7]), \
          "=r"((r)[8]),  "=r"((r)[9]),  "=r"((r)[10]), "=r"((r)[11]), \
          "=r"((r)[12]), "=r"((r)[13]), "=r"((r)[14]), "=r"((r)[15]), \
          "=r"((r)[16]), "=r"((r)[17]), "=r"((r)[18]), "=r"((r)[19]), \
          "=r"((r)[20]), "=r"((r)[21]), "=r"((r)[22]), "=r"((r)[23]), \
          "=r"((r)[24]), "=r"((r)[25]), "=r"((r)[26]), "=r"((r)[27]), \
          "=r"((r)[28]), "=r"((r)[29]), "=r"((r)[30]), "=r"((r)[31]) \
        : "r"(tmem_addr))

#define SWZ128(o) ((o) ^ (((o) >> 3) & 0x70))
static constexpr uint64_t DESC_BASE_SW128 =
    (uint64_t(2) << 61) | (uint64_t(1) << 46) | (uint64_t(64) << 32) | (uint64_t(1) << 16);
__device__ __forceinline__ uint64_t make_desc(uint32_t addr) {
    return DESC_BASE_SW128 | ((uint64_t)(addr >> 4) & 0x3FFF);
}

static constexpr uint32_t IDESC_TF32 =
    (1u << 4) | (2u << 7) | (2u << 10) | ((128u / 8) << 17) | ((128u / 16) << 24);

__device__ __forceinline__ void mma_tf32_ss(uint32_t d, uint64_t a_desc, uint64_t b_desc,
                                            bool accum) {
    uint32_t en = accum ? 1u : 0u;
    asm volatile(
        "{\n\t.reg .pred p;\n\t"
        "setp.ne.u32 p, %5, 0;\n\t"
        "tcgen05.mma.cta_group::1.kind::tf32 [%0], %1, %2, %3, {%4, %4, %4, %4}, p;\n\t"
        "}"
        :: "r"(d), "l"(a_desc), "l"(b_desc), "r"(IDESC_TF32), "r"(0u), "r"(en)
        : "memory");
}
#endif  // HAS_TCGEN05

#if !HAS_TCGEN05
// mma.sync tf32 atom (m16n8k8) — fallback tensor path, legal at compute_103
__device__ __forceinline__ void mma1688(float* d, const uint32_t* a, const uint32_t* b) {
    asm volatile(
        "mma.sync.aligned.m16n8k8.row.col.f32.tf32.tf32.f32 "
        "{%0,%1,%2,%3}, {%4,%5,%6,%7}, {%8,%9}, {%0,%1,%2,%3};"
        : "+f"(d[0]), "+f"(d[1]), "+f"(d[2]), "+f"(d[3])
        : "r"(a[0]), "r"(a[1]), "r"(a[2]), "r"(a[3]), "r"(b[0]), "r"(b[1]));
}
#endif

// ---------------------------------------------------------------------------
// tf32 tensor-core GEMM: C[M,N] = A[M,K] * Bt[N,K]^T (row-major inputs,
// 128x128 CTA tiles, K-chunk 32). Dual path: tcgen05 or mma.sync.
// ---------------------------------------------------------------------------
__global__ void __launch_bounds__(256) gemm_tf32_kernel(
    const float* __restrict__ A, const float* __restrict__ Bt,
    float* __restrict__ C, int M, int N, int K)
{
    extern __shared__ char smem[];
    const int tid = threadIdx.x, wid = tid >> 5, lid = tid & 31;
    const int rowBase = blockIdx.y << 7, colBase = blockIdx.x << 7;

#if HAS_TCGEN05
    // ---------------- tcgen05 path (sm_103a SASS) ----------------
    const uint32_t sbase = smem_u32(smem);
    if (wid == 0) { TCGEN05_ALLOC(sbase, 128); TCGEN05_RELINQUISH(); }
    if (tid == 0) { MBARRIER_INIT(sbase + 8, 1); MBARRIER_INIT(sbase + 16, 1); }
    __syncthreads();
    uint32_t tmem;
    asm volatile("ld.shared.b32 %0, [%1];" : "=r"(tmem) : "r"(sbase));

    const int nchunks = K >> 5;
    int ph0 = 0, ph1 = 0;
    const int SM_A = 1024, SM_B = 1024 + 32768;

    for (int c = 0; c < nchunks; ++c) {
        const int buf = c & 1;
        if (c >= 2) {
            if (buf == 0) { MBARRIER_WAIT_PARITY(sbase + 8, ph0);  ph0 ^= 1; }
            else          { MBARRIER_WAIT_PARITY(sbase + 16, ph1); ph1 ^= 1; }
        }
        const int k0 = c << 5;
        char* abuf = smem + SM_A + buf * 16384;
        char* bbuf = smem + SM_B + buf * 16384;
#pragma unroll
        for (int i = 0; i < 4; ++i) {
            const int f   = tid + i * 256;
            const int row = f >> 3;
            const int c4  = (f & 7) << 2;
            const uint32_t so = SWZ128((row << 7) + (c4 << 2));
            float4 av = *reinterpret_cast<const float4*>(
                &A[(size_t)(rowBase + row) * K + k0 + c4]);
            *reinterpret_cast<float4*>(abuf + so) = av;
            float4 bv = *reinterpret_cast<const float4*>(
                &Bt[(size_t)(colBase + row) * K + k0 + c4]);
            *reinterpret_cast<float4*>(bbuf + so) = bv;
        }
        FENCE_ASYNC();
        __syncthreads();
        if (tid == 0) {
            TCGEN05_FENCE_AFTER();
            const uint64_t ad = make_desc(sbase + SM_A + buf * 16384);
            const uint64_t bd = make_desc(sbase + SM_B + buf * 16384);
#pragma unroll
            for (int k = 0; k < 4; ++k)
                mma_tf32_ss(tmem, ad + k * 2, bd + k * 2, (c | k) != 0);
            TCGEN05_COMMIT(sbase + 8 + buf * 8);
        }
    }

    MBARRIER_WAIT_PARITY(sbase + 8, ph0);
    MBARRIER_WAIT_PARITY(sbase + 16, ph1);
    TCGEN05_FENCE_AFTER();

    const int colOff = (wid >> 2) << 6;
    const int m = rowBase + ((wid & 3) << 5) + lid;
    float* crow = C + (size_t)m * N + colBase + colOff;

    uint32_t d[32];
    TCGEN05_LD_32X32B_X32(d, tmem + colOff);
    TCGEN05_WAIT_LD();
#pragma unroll
    for (int j = 0; j < 8; ++j) {
        float4 v = make_float4(__uint_as_float(d[j*4+0]), __uint_as_float(d[j*4+1]),
                               __uint_as_float(d[j*4+2]), __uint_as_float(d[j*4+3]));
        *reinterpret_cast<float4*>(crow + j * 4) = v;
    }
    TCGEN05_LD_32X32B_X32(d, tmem + colOff + 32);
    TCGEN05_WAIT_LD();
#pragma unroll
    for (int j = 0; j < 8; ++j) {
        float4 v = make_float4(__uint_as_float(d[j*4+0]), __uint_as_float(d[j*4+1]),
                               __uint_as_float(d[j*4+2]), __uint_as_float(d[j*4+3]));
        *reinterpret_cast<float4*>(crow + 32 + j * 4) = v;
    }
    TCGEN05_FENCE_BEFORE();
    __syncthreads();
    if (wid == 0) TCGEN05_DEALLOC(tmem, 128);

#else
    // ---------------- mma.sync fallback path (compute_103) ----------------
    // SMEM: As[2][128][36], Bs[2][128][36] floats. Stride 36 makes the
    // (lane/4, lane%4) fragment pattern bank-conflict-free.
    float (*As)[128][36] = reinterpret_cast<float (*)[128][36]>(smem);
    float (*Bs)[128][36] = reinterpret_cast<float (*)[128][36]>(smem + 36864);
    const uint32_t sb = smem_u32(smem);

    const int wr = wid >> 2;          // warp row (0..1): 64 M-rows
    const int wc = wid & 3;           // warp col (0..3): 32 N-cols
    const int q  = lid >> 2;          // 0..7
    const int cc = lid & 3;           // 0..3

    float acc[4][4][4];
#pragma unroll
    for (int a = 0; a < 4; ++a)
#pragma unroll
        for (int b = 0; b < 4; ++b)
#pragma unroll
            for (int r = 0; r < 4; ++r) acc[a][b][r] = 0.0f;

    const int nchunks = K >> 5;

    auto load_tile = [&](int c, int buf) {
        const int k0 = c << 5;
#pragma unroll
        for (int i = 0; i < 4; ++i) {
            const int f   = tid + i * 256;
            const int row = f >> 3;
            const int c4  = (f & 7) << 2;
            CP_ASYNC16(sb + (buf * 18432) + (row * 36 + c4) * 4,
                       &A[(size_t)(rowBase + row) * K + k0 + c4]);
            CP_ASYNC16(sb + 36864 + (buf * 18432) + (row * 36 + c4) * 4,
                       &Bt[(size_t)(colBase + row) * K + k0 + c4]);
        }
        CP_COMMIT();
    };

    load_tile(0, 0);

    for (int c = 0; c < nchunks; ++c) {
        const int buf = c & 1;
        if (c + 1 < nchunks) {
            load_tile(c + 1, (c + 1) & 1);
            CP_WAIT_1();
        } else {
            CP_WAIT_0();
        }
        __syncthreads();

#pragma unroll
        for (int ks = 0; ks < 4; ++ks) {
            uint32_t bf[4][2];
#pragma unroll
            for (int nt = 0; nt < 4; ++nt) {
                bf[nt][0] = __float_as_uint(Bs[buf][wc * 32 + nt * 8 + q][ks * 8 + cc]);
                bf[nt][1] = __float_as_uint(Bs[buf][wc * 32 + nt * 8 + q][ks * 8 + cc + 4]);
            }
#pragma unroll
            for (int mt = 0; mt < 4; ++mt) {
                const int r0 = wr * 64 + mt * 16 + q;
                uint32_t af[4];
                af[0] = __float_as_uint(As[buf][r0    ][ks * 8 + cc]);
                af[1] = __float_as_uint(As[buf][r0 + 8][ks * 8 + cc]);
                af[2] = __float_as_uint(As[buf][r0    ][ks * 8 + cc + 4]);
                af[3] = __float_as_uint(As[buf][r0 + 8][ks * 8 + cc + 4]);
#pragma unroll
                for (int nt = 0; nt < 4; ++nt)
                    mma1688(acc[mt][nt], af, bf[nt]);
            }
        }
        __syncthreads();
    }

#pragma unroll
    for (int mt = 0; mt < 4; ++mt) {
        const int row = rowBase + wr * 64 + mt * 16 + q;
#pragma unroll
        for (int nt = 0; nt < 4; ++nt) {
            const int col = colBase + wc * 32 + nt * 8 + 2 * cc;
            *reinterpret_cast<float2*>(&C[(size_t)row * N + col]) =
                make_float2(acc[mt][nt][0], acc[mt][nt][1]);
            *reinterpret_cast<float2*>(&C[(size_t)(row + 8) * N + col]) =
                make_float2(acc[mt][nt][2], acc[mt][nt][3]);
        }
    }
#endif
}

// ---------------------------------------------------------------------------
// Pre-passes: tf32 rounding + weight transpose
// ---------------------------------------------------------------------------
__global__ void __launch_bounds__(256) cvt_tf32_kernel(
    const float4* __restrict__ in, float4* __restrict__ out, int n4)
{
    int i = blockIdx.x * blockDim.x + threadIdx.x;
    if (i < n4) {
        float4 v = in[i];
        v.x = to_tf32(v.x); v.y = to_tf32(v.y);
        v.z = to_tf32(v.z); v.w = to_tf32(v.w);
        out[i] = v;
    }
}

// W[K][N] row-major -> Wt[N][K] row-major, rounded to tf32
__global__ void __launch_bounds__(256) transpose_tf32_kernel(
    const float* __restrict__ W, float* __restrict__ Wt, int K, int N)
{
    __shared__ float t[32][33];
    const int n0 = blockIdx.x * 32, k0 = blockIdx.y * 32;
    const int tx = threadIdx.x, ty = threadIdx.y;   // 32 x 8
#pragma unroll
    for (int i = 0; i < 4; ++i)
        t[ty + i * 8][tx] = W[(size_t)(k0 + ty + i * 8) * N + n0 + tx];
    __syncthreads();
#pragma unroll
    for (int i = 0; i < 4; ++i)
        Wt[(size_t)(n0 + ty + i * 8) * K + k0 + tx] = to_tf32(t[tx][ty + i * 8]);
}

// ---------------------------------------------------------------------------
// Causal flash attention, chunked online softmax.
// One CTA per (q-tile 64, head, batch); 64 threads, one query row each.
// Scores computed in 16-wide chunks -> one o-rescale per chunk (not per j),
// 4-way split dot-product accumulators for ILP.
// ---------------------------------------------------------------------------
__global__ void __launch_bounds__(64) attn_kernel(
    const float* __restrict__ qkv, float* __restrict__ out)
{
    __shared__ float Qs[DHEAD][64];   // Qs[i][row]
    __shared__ float Ks[64][DHEAD];
    __shared__ float Vs[64][DHEAD];

    const int tid = threadIdx.x;
    const int rt  = blockIdx.x;
    const int h   = blockIdx.y;
    const int b   = blockIdx.z;

    const size_t rowStride = QKVCOLS;
    const float* qbase = qkv + ((size_t)b * SEQ + (size_t)rt * 64) * rowStride + h * DHEAD;

#pragma unroll 8
    for (int i = 0; i < DHEAD; ++i)
        Qs[i][tid] = qbase[(size_t)tid * rowStride + i];

    float o[DHEAD];
#pragma unroll
    for (int i = 0; i < DHEAD; ++i) o[i] = 0.0f;
    float m = -INFINITY, l = 0.0f;

    const int q_row = rt * 64 + tid;
    const float scale = 0.125f;   // 1/sqrt(64)

    for (int kt = 0; kt <= rt; ++kt) {
        const float* kbase = qkv + ((size_t)b * SEQ + (size_t)kt * 64) * rowStride
                                 + DMODEL + h * DHEAD;
        __syncthreads();
        for (int r = 0; r < 64; ++r) {
            Ks[r][tid] = kbase[(size_t)r * rowStride + tid];
            Vs[r][tid] = kbase[(size_t)r * rowStride + DMODEL + tid];
        }
        __syncthreads();

        const bool masked_tile = (kt == rt);

        for (int jc = 0; jc < 4; ++jc) {         // 16-wide score chunks
            float s[16];
            float cmax = -INFINITY;
#pragma unroll
            for (int jj = 0; jj < 16; ++jj) {
                const int j = jc * 16 + jj;
                float a0 = 0.f, a1 = 0.f, a2 = 0.f, a3 = 0.f;
#pragma unroll
                for (int i = 0; i < DHEAD; i += 4) {
                    a0 = fmaf(Qs[i + 0][tid], Ks[j][i + 0], a0);
                    a1 = fmaf(Qs[i + 1][tid], Ks[j][i + 1], a1);
                    a2 = fmaf(Qs[i + 2][tid], Ks[j][i + 2], a2);
                    a3 = fmaf(Qs[i + 3][tid], Ks[j][i + 3], a3);
                }
                float sv = ((a0 + a1) + (a2 + a3)) * scale;
                if (masked_tile && (kt * 64 + j) > q_row) sv = -INFINITY;
                s[jj] = sv;
                cmax = fmaxf(cmax, sv);
            }

            const float mnew = fmaxf(m, cmax);
            if (mnew == -INFINITY) continue;     // chunk fully masked, nothing yet
            const float corr = __expf(m - mnew); // m=-inf -> corr=0 (safe: mnew>-inf)
            l *= corr;
#pragma unroll
            for (int i = 0; i < DHEAD; ++i) o[i] *= corr;
#pragma unroll
            for (int jj = 0; jj < 16; ++jj) {
                const int j = jc * 16 + jj;
                const float p = __expf(s[jj] - mnew);   // masked -> exp(-inf)=0
                l += p;
#pragma unroll
                for (int i = 0; i < DHEAD; ++i)
                    o[i] = fmaf(p, Vs[j][i], o[i]);
            }
            m = mnew;
        }
    }

    const float inv_l = 1.0f / l;
    float* obase = out + ((size_t)b * SEQ + q_row) * DMODEL + h * DHEAD;
#pragma unroll 8
    for (int i = 0; i < DHEAD; ++i)
        obase[i] = to_tf32(o[i] * inv_l);   // pre-round for GEMM2
}

// ---------------------------------------------------------------------------
extern "C" void kernel_launch(void* const* d_in, const int* in_sizes, int n_in,
                              void* d_out, int out_size)
{
    const float* x     = (const float*)d_in[0];  // [4,2048,1024]
    const float* W_qkv = (const float*)d_in[1];  // [1024,3072]
    const float* W_out = (const float*)d_in[2];  // [1024,1024]
    float* out = (float*)d_out;                  // [4,2048,1024]

    float *xc, *qkv, *attn, *wqkvT, *woutT;
    cudaGetSymbolAddress((void**)&xc,    g_xc);
    cudaGetSymbolAddress((void**)&qkv,   g_qkv);
    cudaGetSymbolAddress((void**)&attn,  g_attn);
    cudaGetSymbolAddress((void**)&wqkvT, g_wqkvT);
    cudaGetSymbolAddress((void**)&woutT, g_woutT);

    cudaFuncSetAttribute(gemm_tf32_kernel,
                         cudaFuncAttributeMaxDynamicSharedMemorySize, GEMM_SMEM);

    // Pre-passes: tf32 rounding of activations, transposed+rounded weights
    const int n4 = MROWS * DMODEL / 4;
    cvt_tf32_kernel<<<n4 / 256, 256>>>((const float4*)x, (float4*)xc, n4);
    transpose_tf32_kernel<<<dim3(QKVCOLS / 32, DMODEL / 32), dim3(32, 8)>>>(
        W_qkv, wqkvT, DMODEL, QKVCOLS);
    transpose_tf32_kernel<<<dim3(DMODEL / 32, DMODEL / 32), dim3(32, 8)>>>(
        W_out, woutT, DMODEL, DMODEL);

    // 1) QKV projection (tensor cores, tf32): [8192,1024] @ [1024,3072]
    gemm_tf32_kernel<<<dim3(QKVCOLS / 128, MROWS / 128), 256, GEMM_SMEM>>>(
        xc, wqkvT, qkv, MROWS, QKVCOLS, DMODEL);

    // 2) Causal multi-head attention (fp32 FFMA, chunked softmax)
    attn_kernel<<<dim3(SEQ / 64, NHEADS, BSZ), 64>>>(qkv, attn);

    // 3) Output projection (tensor cores, tf32): [8192,1024] @ [1024,1024]
    gemm_tf32_kernel<<<dim3(DMODEL / 128, MROWS / 128), 256, GEMM_SMEM>>>(
        attn, woutT, out, MROWS, DMODEL, DMODEL);
}

// round 5
// speedup vs baseline: 4.3192x; 2.6801x over previous
#include <cuda_runtime.h>
#include <cstdint>
#include <math.h>

// Problem constants
#define BSZ 4
#define SEQ 2048
#define DMODEL 1024
#define NHEADS 16
#define DHEAD 64
#define QKVCOLS (3 * DMODEL)          // 3072
#define MROWS (BSZ * SEQ)             // 8192

// Scratch (device globals: the only sanctioned scratch mechanism)
__device__ float g_xc   [(size_t)MROWS * DMODEL];     // x rounded to tf32
__device__ float g_qkv  [(size_t)MROWS * QKVCOLS];    // QKV, tf32-rounded
__device__ float g_attn [(size_t)MROWS * DMODEL];     // attention out (tf32-rounded)
__device__ float g_wqkvT[(size_t)QKVCOLS * DMODEL];   // W_qkv^T, tf32
__device__ float g_woutT[(size_t)DMODEL * DMODEL];    // W_out^T, tf32

// ---------------------------------------------------------------------------
// Helpers
// ---------------------------------------------------------------------------
__device__ __forceinline__ float to_tf32(float x) {
    uint32_t u; asm("cvt.rna.tf32.f32 %0, %1;" : "=r"(u) : "f"(x));
    return __uint_as_float(u);
}
__device__ __forceinline__ uint32_t smem_u32(const void* p) {
    uint32_t a;
    asm("{ .reg .u64 t; cvta.to.shared.u64 t, %1; cvt.u32.u64 %0, t; }"
        : "=r"(a) : "l"(p));
    return a;
}

#define CP_ASYNC16(dst_u32, src_ptr) \
    asm volatile("cp.async.ca.shared.global [%0], [%1], 16;" \
                 :: "r"(dst_u32), "l"(src_ptr) : "memory")
#define CP_COMMIT() asm volatile("cp.async.commit_group;" ::: "memory")
#define CP_WAIT_1() asm volatile("cp.async.wait_group 1;" ::: "memory")
#define CP_WAIT_0() asm volatile("cp.async.wait_group 0;" ::: "memory")

// mma.sync tf32 atom (m16n8k8) — tensor path legal at compute_103
__device__ __forceinline__ void mma1688(float* d, const uint32_t* a, const uint32_t* b) {
    asm volatile(
        "mma.sync.aligned.m16n8k8.row.col.f32.tf32.tf32.f32 "
        "{%0,%1,%2,%3}, {%4,%5,%6,%7}, {%8,%9}, {%0,%1,%2,%3};"
        : "+f"(d[0]), "+f"(d[1]), "+f"(d[2]), "+f"(d[3])
        : "r"(a[0]), "r"(a[1]), "r"(a[2]), "r"(a[3]), "r"(b[0]), "r"(b[1]));
}

#define GEMM_SMEM 73728

// ---------------------------------------------------------------------------
// tf32 tensor-core GEMM: C[M,N] = A[M,K] * Bt[N,K]^T
// 128x128 CTA tiles, K-chunk 32, cp.async double-buffered. 8 warps, each a
// 64x32 warp tile of m16n8k8 atoms. round_out: tf32-round the output.
// ---------------------------------------------------------------------------
__global__ void __launch_bounds__(256) gemm_tf32_kernel(
    const float* __restrict__ A, const float* __restrict__ Bt,
    float* __restrict__ C, int M, int N, int K, int round_out)
{
    extern __shared__ char smem[];
    const int tid = threadIdx.x, wid = tid >> 5, lid = tid & 31;
    const int rowBase = blockIdx.y << 7, colBase = blockIdx.x << 7;

    // SMEM: As[2][128][36], Bs[2][128][36] floats. Stride 36 keeps the
    // (lane/4, lane%4) fragment pattern bank-conflict-free.
    float (*As)[128][36] = reinterpret_cast<float (*)[128][36]>(smem);
    float (*Bs)[128][36] = reinterpret_cast<float (*)[128][36]>(smem + 36864);
    const uint32_t sb = smem_u32(smem);

    const int wr = wid >> 2;          // warp row (0..1): 64 M-rows
    const int wc = wid & 3;           // warp col (0..3): 32 N-cols
    const int q  = lid >> 2;          // 0..7
    const int cc = lid & 3;           // 0..3

    float acc[4][4][4];
#pragma unroll
    for (int a = 0; a < 4; ++a)
#pragma unroll
        for (int b = 0; b < 4; ++b)
#pragma unroll
            for (int r = 0; r < 4; ++r) acc[a][b][r] = 0.0f;

    const int nchunks = K >> 5;

    auto load_tile = [&](int c, int buf) {
        const int k0 = c << 5;
#pragma unroll
        for (int i = 0; i < 4; ++i) {
            const int f   = tid + i * 256;
            const int row = f >> 3;
            const int c4  = (f & 7) << 2;
            CP_ASYNC16(sb + (buf * 18432) + (row * 36 + c4) * 4,
                       &A[(size_t)(rowBase + row) * K + k0 + c4]);
            CP_ASYNC16(sb + 36864 + (buf * 18432) + (row * 36 + c4) * 4,
                       &Bt[(size_t)(colBase + row) * K + k0 + c4]);
        }
        CP_COMMIT();
    };

    load_tile(0, 0);

    for (int c = 0; c < nchunks; ++c) {
        const int buf = c & 1;
        if (c + 1 < nchunks) {
            load_tile(c + 1, (c + 1) & 1);
            CP_WAIT_1();
        } else {
            CP_WAIT_0();
        }
        __syncthreads();

#pragma unroll
        for (int ks = 0; ks < 4; ++ks) {
            uint32_t bf[4][2];
#pragma unroll
            for (int nt = 0; nt < 4; ++nt) {
                bf[nt][0] = __float_as_uint(Bs[buf][wc * 32 + nt * 8 + q][ks * 8 + cc]);
                bf[nt][1] = __float_as_uint(Bs[buf][wc * 32 + nt * 8 + q][ks * 8 + cc + 4]);
            }
#pragma unroll
            for (int mt = 0; mt < 4; ++mt) {
                const int r0 = wr * 64 + mt * 16 + q;
                uint32_t af[4];
                af[0] = __float_as_uint(As[buf][r0    ][ks * 8 + cc]);
                af[1] = __float_as_uint(As[buf][r0 + 8][ks * 8 + cc]);
                af[2] = __float_as_uint(As[buf][r0    ][ks * 8 + cc + 4]);
                af[3] = __float_as_uint(As[buf][r0 + 8][ks * 8 + cc + 4]);
#pragma unroll
                for (int nt = 0; nt < 4; ++nt)
                    mma1688(acc[mt][nt], af, bf[nt]);
            }
        }
        __syncthreads();
    }

#pragma unroll
    for (int mt = 0; mt < 4; ++mt) {
        const int row = rowBase + wr * 64 + mt * 16 + q;
#pragma unroll
        for (int nt = 0; nt < 4; ++nt) {
            const int col = colBase + wc * 32 + nt * 8 + 2 * cc;
            float v0 = acc[mt][nt][0], v1 = acc[mt][nt][1];
            float v2 = acc[mt][nt][2], v3 = acc[mt][nt][3];
            if (round_out) {
                v0 = to_tf32(v0); v1 = to_tf32(v1);
                v2 = to_tf32(v2); v3 = to_tf32(v3);
            }
            *reinterpret_cast<float2*>(&C[(size_t)row * N + col]) = make_float2(v0, v1);
            *reinterpret_cast<float2*>(&C[(size_t)(row + 8) * N + col]) = make_float2(v2, v3);
        }
    }
}

// ---------------------------------------------------------------------------
// Pre-passes: tf32 rounding + weight transpose
// ---------------------------------------------------------------------------
__global__ void __launch_bounds__(256) cvt_tf32_kernel(
    const float4* __restrict__ in, float4* __restrict__ out, int n4)
{
    int i = blockIdx.x * blockDim.x + threadIdx.x;
    if (i < n4) {
        float4 v = in[i];
        v.x = to_tf32(v.x); v.y = to_tf32(v.y);
        v.z = to_tf32(v.z); v.w = to_tf32(v.w);
        out[i] = v;
    }
}

__global__ void __launch_bounds__(256) transpose_tf32_kernel(
    const float* __restrict__ W, float* __restrict__ Wt, int K, int N)
{
    __shared__ float t[32][33];
    const int n0 = blockIdx.x * 32, k0 = blockIdx.y * 32;
    const int tx = threadIdx.x, ty = threadIdx.y;   // 32 x 8
#pragma unroll
    for (int i = 0; i < 4; ++i)
        t[ty + i * 8][tx] = W[(size_t)(k0 + ty + i * 8) * N + n0 + tx];
    __syncthreads();
#pragma unroll
    for (int i = 0; i < 4; ++i)
        Wt[(size_t)(n0 + ty + i * 8) * K + k0 + tx] = to_tf32(t[tx][ty + i * 8]);
}

// ---------------------------------------------------------------------------
// Tensor-core causal flash attention (FA2 style, mma.sync tf32).
// Grid: (16 q-tiles of 128, 16 heads, 4 batch). 256 threads = 8 warps.
// Warp w owns Q rows [qb + 16w, qb + 16w + 16). Q resident in a-frag regs
// (pre-scaled by 1/8). KV in 64-row tiles, cp.async double-buffered, rows
// padded to stride 68 floats (16B-aligned, conflict-free K b-frag reads).
// P staged through per-warp SMEM to convert c-layout -> a-layout.
// Requires qkv tf32-rounded (GEMM1 epilogue does this).
// ---------------------------------------------------------------------------
#define KVSTRIDE 68
#define KVBUF (64 * KVSTRIDE)                    // floats per K or V buffer
#define ATTN_SMEM ((4 * KVBUF + 8 * 16 * KVSTRIDE) * 4)   // 104448 bytes

__global__ void __launch_bounds__(256) attn_mma_kernel(
    const float* __restrict__ qkv, float* __restrict__ out)
{
    extern __shared__ float sm[];
    float* Pst = sm + 4 * KVBUF;                 // [8 warps][16][KVSTRIDE]

    const int tid = threadIdx.x, wq = tid >> 5, lane = tid & 31;
    const int q = lane >> 2, cc = lane & 3;
    const int rt = blockIdx.x, h = blockIdx.y, b = blockIdx.z;
    const int qb = rt * 128;
    const int nkt = 2 * rt + 2;                  // causal kv tile count
    const float* base = qkv + (size_t)b * SEQ * QKVCOLS;
    const uint32_t smb = smem_u32(sm);

    // --- resident Q fragments, pre-scaled by 1/8 (exact) ---
    uint32_t aq[8][4];
    {
        const int r0 = qb + wq * 16 + q;
#pragma unroll
        for (int ks = 0; ks < 8; ++ks)
#pragma unroll
            for (int e = 0; e < 4; ++e) {
                const int row = r0 + (e & 1) * 8;
                const int col = h * DHEAD + 8 * ks + cc + (e >> 1) * 4;
                aq[ks][e] = __float_as_uint(
                    0.125f * base[(size_t)row * QKVCOLS + col]);
            }
    }

    float oacc[8][4];
#pragma unroll
    for (int nt = 0; nt < 8; ++nt)
#pragma unroll
        for (int e = 0; e < 4; ++e) oacc[nt][e] = 0.0f;
    float m0 = -INFINITY, m1 = -INFINITY, l0 = 0.0f, l1 = 0.0f;

    auto cptile = [&](int kt, int bufsel) {
        const float* kS = base + (size_t)(kt * 64) * QKVCOLS + DMODEL + h * DHEAD;
        const float* vS = base + (size_t)(kt * 64) * QKVCOLS + 2 * DMODEL + h * DHEAD;
        const uint32_t kD = smb + (uint32_t)bufsel * KVBUF * 4;
        const uint32_t vD = smb + (2u + bufsel) * KVBUF * 4;
#pragma unroll
        for (int i = 0; i < 4; ++i) {
            const int ch  = tid + i * 256;
            const int row = ch >> 4;
            const int c4  = (ch & 15) << 2;
            CP_ASYNC16(kD + (row * KVSTRIDE + c4) * 4, kS + (size_t)row * QKVCOLS + c4);
            CP_ASYNC16(vD + (row * KVSTRIDE + c4) * 4, vS + (size_t)row * QKVCOLS + c4);
        }
        CP_COMMIT();
    };

    cptile(0, 0);

    for (int kt = 0; kt < nkt; ++kt) {
        const int buf = kt & 1;
        if (kt + 1 < nkt) { cptile(kt + 1, (kt + 1) & 1); CP_WAIT_1(); }
        else              { CP_WAIT_0(); }
        __syncthreads();

        const float* Kb = sm + buf * KVBUF;
        const float* Vb = sm + (2 + buf) * KVBUF;

        // ---- S = (Q/8) K^T ----
        float sacc[8][4];
#pragma unroll
        for (int nt = 0; nt < 8; ++nt) {
            sacc[nt][0] = sacc[nt][1] = sacc[nt][2] = sacc[nt][3] = 0.0f;
#pragma unroll
            for (int ks = 0; ks < 8; ++ks) {
                uint32_t bb[2];
                bb[0] = __float_as_uint(Kb[(8 * nt + q) * KVSTRIDE + 8 * ks + cc]);
                bb[1] = __float_as_uint(Kb[(8 * nt + q) * KVSTRIDE + 8 * ks + cc + 4]);
                mma1688(sacc[nt], aq[ks], bb);
            }
        }

        // ---- causal mask (diagonal tiles only) ----
        if (kt * 64 + 63 > qb + wq * 16) {
            const int r0g = qb + wq * 16 + q, r1g = r0g + 8;
#pragma unroll
            for (int nt = 0; nt < 8; ++nt) {
                const int c0g = kt * 64 + 8 * nt + 2 * cc;
                if (c0g     > r0g) sacc[nt][0] = -INFINITY;
                if (c0g + 1 > r0g) sacc[nt][1] = -INFINITY;
                if (c0g     > r1g) sacc[nt][2] = -INFINITY;
                if (c0g + 1 > r1g) sacc[nt][3] = -INFINITY;
            }
        }

        // ---- online softmax (row max quad-reduced; l kept thread-partial) ----
        float cm0 = -INFINITY, cm1 = -INFINITY;
#pragma unroll
        for (int nt = 0; nt < 8; ++nt) {
            cm0 = fmaxf(cm0, fmaxf(sacc[nt][0], sacc[nt][1]));
            cm1 = fmaxf(cm1, fmaxf(sacc[nt][2], sacc[nt][3]));
        }
        cm0 = fmaxf(cm0, __shfl_xor_sync(0xffffffffu, cm0, 1));
        cm0 = fmaxf(cm0, __shfl_xor_sync(0xffffffffu, cm0, 2));
        cm1 = fmaxf(cm1, __shfl_xor_sync(0xffffffffu, cm1, 1));
        cm1 = fmaxf(cm1, __shfl_xor_sync(0xffffffffu, cm1, 2));

        const float mn0 = fmaxf(m0, cm0), mn1 = fmaxf(m1, cm1);
        const float corr0 = __expf(m0 - mn0), corr1 = __expf(m1 - mn1);

        float* pw = Pst + wq * (16 * KVSTRIDE);
        float ps0 = 0.0f, ps1 = 0.0f;
#pragma unroll
        for (int nt = 0; nt < 8; ++nt) {
            const float p0 = __expf(sacc[nt][0] - mn0);
            const float p1 = __expf(sacc[nt][1] - mn0);
            const float p2 = __expf(sacc[nt][2] - mn1);
            const float p3 = __expf(sacc[nt][3] - mn1);
            ps0 += p0 + p1; ps1 += p2 + p3;
            *reinterpret_cast<float2*>(&pw[q * KVSTRIDE + 8 * nt + 2 * cc]) =
                make_float2(to_tf32(p0), to_tf32(p1));
            *reinterpret_cast<float2*>(&pw[(q + 8) * KVSTRIDE + 8 * nt + 2 * cc]) =
                make_float2(to_tf32(p2), to_tf32(p3));
            oacc[nt][0] *= corr0; oacc[nt][1] *= corr0;
            oacc[nt][2] *= corr1; oacc[nt][3] *= corr1;
        }
        l0 = l0 * corr0 + ps0;
        l1 = l1 * corr1 + ps1;
        m0 = mn0; m1 = mn1;
        __syncwarp();

        // ---- O += P V ----
#pragma unroll
        for (int ks = 0; ks < 8; ++ks) {
            uint32_t ap[4];
            ap[0] = __float_as_uint(pw[ q      * KVSTRIDE + 8 * ks + cc]);
            ap[1] = __float_as_uint(pw[(q + 8) * KVSTRIDE + 8 * ks + cc]);
            ap[2] = __float_as_uint(pw[ q      * KVSTRIDE + 8 * ks + cc + 4]);
            ap[3] = __float_as_uint(pw[(q + 8) * KVSTRIDE + 8 * ks + cc + 4]);
#pragma unroll
            for (int nt = 0; nt < 8; ++nt) {
                uint32_t bb[2];
                bb[0] = __float_as_uint(Vb[(8 * ks + cc)     * KVSTRIDE + 8 * nt + q]);
                bb[1] = __float_as_uint(Vb[(8 * ks + cc + 4) * KVSTRIDE + 8 * nt + q]);
                mma1688(oacc[nt], ap, bb);
            }
        }
        __syncthreads();   // all warps done reading buf before it is refilled
    }

    // ---- epilogue: reduce l across quad, normalize, store (tf32-rounded) ----
    l0 += __shfl_xor_sync(0xffffffffu, l0, 1);
    l0 += __shfl_xor_sync(0xffffffffu, l0, 2);
    l1 += __shfl_xor_sync(0xffffffffu, l1, 1);
    l1 += __shfl_xor_sync(0xffffffffu, l1, 2);
    const float inv0 = 1.0f / l0, inv1 = 1.0f / l1;

    float* ob = out + (size_t)(b * SEQ + qb + wq * 16 + q) * DMODEL + h * DHEAD;
#pragma unroll
    for (int nt = 0; nt < 8; ++nt) {
        *reinterpret_cast<float2*>(&ob[8 * nt + 2 * cc]) =
            make_float2(to_tf32(oacc[nt][0] * inv0), to_tf32(oacc[nt][1] * inv0));
        *reinterpret_cast<float2*>(&ob[(size_t)8 * DMODEL + 8 * nt + 2 * cc]) =
            make_float2(to_tf32(oacc[nt][2] * inv1), to_tf32(oacc[nt][3] * inv1));
    }
}

// ---------------------------------------------------------------------------
extern "C" void kernel_launch(void* const* d_in, const int* in_sizes, int n_in,
                              void* d_out, int out_size)
{
    const float* x     = (const float*)d_in[0];  // [4,2048,1024]
    const float* W_qkv = (const float*)d_in[1];  // [1024,3072]
    const float* W_out = (const float*)d_in[2];  // [1024,1024]
    float* out = (float*)d_out;                  // [4,2048,1024]

    float *xc, *qkv, *attn, *wqkvT, *woutT;
    cudaGetSymbolAddress((void**)&xc,    g_xc);
    cudaGetSymbolAddress((void**)&qkv,   g_qkv);
    cudaGetSymbolAddress((void**)&attn,  g_attn);
    cudaGetSymbolAddress((void**)&wqkvT, g_wqkvT);
    cudaGetSymbolAddress((void**)&woutT, g_woutT);

    cudaFuncSetAttribute(gemm_tf32_kernel,
                         cudaFuncAttributeMaxDynamicSharedMemorySize, GEMM_SMEM);
    cudaFuncSetAttribute(attn_mma_kernel,
                         cudaFuncAttributeMaxDynamicSharedMemorySize, ATTN_SMEM);

    // Pre-passes
    const int n4 = MROWS * DMODEL / 4;
    cvt_tf32_kernel<<<n4 / 256, 256>>>((const float4*)x, (float4*)xc, n4);
    transpose_tf32_kernel<<<dim3(QKVCOLS / 32, DMODEL / 32), dim3(32, 8)>>>(
        W_qkv, wqkvT, DMODEL, QKVCOLS);
    transpose_tf32_kernel<<<dim3(DMODEL / 32, DMODEL / 32), dim3(32, 8)>>>(
        W_out, woutT, DMODEL, DMODEL);

    // 1) QKV projection (tf32 tensor cores), output tf32-rounded for attention
    gemm_tf32_kernel<<<dim3(QKVCOLS / 128, MROWS / 128), 256, GEMM_SMEM>>>(
        xc, wqkvT, qkv, MROWS, QKVCOLS, DMODEL, 1);

    // 2) Tensor-core causal flash attention
    attn_mma_kernel<<<dim3(SEQ / 128, NHEADS, BSZ), 256, ATTN_SMEM>>>(qkv, attn);

    // 3) Output projection (tf32 tensor cores)
    gemm_tf32_kernel<<<dim3(DMODEL / 128, MROWS / 128), 256, GEMM_SMEM>>>(
        attn, woutT, out, MROWS, DMODEL, DMODEL, 0);
}

// round 6
// speedup vs baseline: 4.3568x; 1.0087x over previous
#include <cuda_runtime.h>
#include <cuda_fp16.h>
#include <cstdint>
#include <math.h>

// Problem constants
#define BSZ 4
#define SEQ 2048
#define DMODEL 1024
#define NHEADS 16
#define DHEAD 64
#define QKVCOLS (3 * DMODEL)          // 3072
#define MROWS (BSZ * SEQ)             // 8192

// Scratch (device globals)
__device__ float  g_xc   [(size_t)MROWS * DMODEL];    // x, tf32, pair-permuted K-layout
__device__ float  g_qkv  [(size_t)MROWS * QKVCOLS];   // Q,K tf32 pair-permuted (V region unused)
__device__ float  g_attn [(size_t)MROWS * DMODEL];    // attn out, tf32, pair-permuted
__device__ float  g_wqkvT[(size_t)QKVCOLS * DMODEL];  // W_qkv^T, tf32, pair-permuted
__device__ float  g_woutT[(size_t)DMODEL * DMODEL];   // W_out^T, tf32, pair-permuted
__device__ __half g_vh   [(size_t)BSZ * NHEADS * DHEAD * SEQ];  // V^T fp16 [b][h][d][t]

// ---------------------------------------------------------------------------
// Helpers
// ---------------------------------------------------------------------------
__device__ __forceinline__ float to_tf32(float x) {
    uint32_t u; asm("cvt.rna.tf32.f32 %0, %1;" : "=r"(u) : "f"(x));
    return __uint_as_float(u);
}
__device__ __forceinline__ uint32_t smem_u32(const void* p) {
    uint32_t a;
    asm("{ .reg .u64 t; cvta.to.shared.u64 t, %1; cvt.u32.u64 %0, t; }"
        : "=r"(a) : "l"(p));
    return a;
}
__device__ __forceinline__ uint32_t pack_h2(float a, float b) {
    __half2 h = __floats2half2_rn(a, b);
    return *reinterpret_cast<uint32_t*>(&h);
}
// In-group position after pair permutation [0,4,1,5,2,6,3,7]
__device__ __forceinline__ int permpos(int c) { return (c < 4) ? 2 * c : 2 * c - 7; }

#define CP_ASYNC16(dst_u32, src_ptr) \
    asm volatile("cp.async.ca.shared.global [%0], [%1], 16;" \
                 :: "r"(dst_u32), "l"(src_ptr) : "memory")
#define CP_COMMIT() asm volatile("cp.async.commit_group;" ::: "memory")
#define CP_WAIT_1() asm volatile("cp.async.wait_group 1;" ::: "memory")
#define CP_WAIT_0() asm volatile("cp.async.wait_group 0;" ::: "memory")

// tf32 m16n8k8 (tensor pipe, legal at compute_103)
__device__ __forceinline__ void mma1688(float* d, const uint32_t* a, const uint32_t* b) {
    asm volatile(
        "mma.sync.aligned.m16n8k8.row.col.f32.tf32.tf32.f32 "
        "{%0,%1,%2,%3}, {%4,%5,%6,%7}, {%8,%9}, {%0,%1,%2,%3};"
        : "+f"(d[0]), "+f"(d[1]), "+f"(d[2]), "+f"(d[3])
        : "r"(a[0]), "r"(a[1]), "r"(a[2]), "r"(a[3]), "r"(b[0]), "r"(b[1]));
}
// fp16 m16n8k16, f32 accumulate
__device__ __forceinline__ void mma16816h(float* d, const uint32_t* a,
                                          uint32_t b0, uint32_t b1) {
    asm volatile(
        "mma.sync.aligned.m16n8k16.row.col.f32.f16.f16.f32 "
        "{%0,%1,%2,%3}, {%4,%5,%6,%7}, {%8,%9}, {%0,%1,%2,%3};"
        : "+f"(d[0]), "+f"(d[1]), "+f"(d[2]), "+f"(d[3])
        : "r"(a[0]), "r"(a[1]), "r"(a[2]), "r"(a[3]), "r"(b0), "r"(b1));
}

#define GEMM_SMEM 73728

// ---------------------------------------------------------------------------
// tf32 GEMM: C[M,N] = A[M,K] * Bt[N,K]^T. A and Bt are tf32, pair-permuted
// along K. 128x128 CTA tiles, BK=32, cp.async double buffer, 8 warps 64x32.
// mode 0: plain f32 output. mode 1: QKV special (cols<2048 -> permuted tf32
// into qkv; cols>=2048 -> fp16 V^T into g_vh).
// ---------------------------------------------------------------------------
__global__ void __launch_bounds__(256) gemm_tf32_kernel(
    const float* __restrict__ A, const float* __restrict__ Bt,
    float* __restrict__ C, __half* __restrict__ vh,
    int M, int N, int K, int mode)
{
    extern __shared__ char smem[];
    const int tid = threadIdx.x, wid = tid >> 5, lid = tid & 31;
    const int rowBase = blockIdx.y << 7, colBase = blockIdx.x << 7;

    float (*As)[128][36] = reinterpret_cast<float (*)[128][36]>(smem);
    float (*Bs)[128][36] = reinterpret_cast<float (*)[128][36]>(smem + 36864);
    const uint32_t sb = smem_u32(smem);

    const int wr = wid >> 2, wc = wid & 3;
    const int q = lid >> 2, cc = lid & 3;

    float acc[4][4][4];
#pragma unroll
    for (int a = 0; a < 4; ++a)
#pragma unroll
        for (int b = 0; b < 4; ++b)
#pragma unroll
            for (int r = 0; r < 4; ++r) acc[a][b][r] = 0.0f;

    const int nchunks = K >> 5;

    auto load_tile = [&](int c, int buf) {
        const int k0 = c << 5;
#pragma unroll
        for (int i = 0; i < 4; ++i) {
            const int f   = tid + i * 256;
            const int row = f >> 3;
            const int c4  = (f & 7) << 2;
            CP_ASYNC16(sb + (buf * 18432) + (row * 36 + c4) * 4,
                       &A[(size_t)(rowBase + row) * K + k0 + c4]);
            CP_ASYNC16(sb + 36864 + (buf * 18432) + (row * 36 + c4) * 4,
                       &Bt[(size_t)(colBase + row) * K + k0 + c4]);
        }
        CP_COMMIT();
    };

    load_tile(0, 0);

    for (int c = 0; c < nchunks; ++c) {
        const int buf = c & 1;
        if (c + 1 < nchunks) { load_tile(c + 1, (c + 1) & 1); CP_WAIT_1(); }
        else                 { CP_WAIT_0(); }
        __syncthreads();

#pragma unroll
        for (int ks = 0; ks < 4; ++ks) {
            // permuted layout: pair (cc, cc+4) adjacent at 8ks+2cc -> LDS.64
            float2 bv[4];
#pragma unroll
            for (int nt = 0; nt < 4; ++nt)
                bv[nt] = *reinterpret_cast<const float2*>(
                    &Bs[buf][wc * 32 + nt * 8 + q][ks * 8 + 2 * cc]);
#pragma unroll
            for (int mt = 0; mt < 4; ++mt) {
                const int r0 = wr * 64 + mt * 16 + q;
                float2 a0 = *reinterpret_cast<const float2*>(
                    &As[buf][r0][ks * 8 + 2 * cc]);
                float2 a1 = *reinterpret_cast<const float2*>(
                    &As[buf][r0 + 8][ks * 8 + 2 * cc]);
                uint32_t af[4] = { __float_as_uint(a0.x), __float_as_uint(a1.x),
                                   __float_as_uint(a0.y), __float_as_uint(a1.y) };
#pragma unroll
                for (int nt = 0; nt < 4; ++nt) {
                    uint32_t bb[2] = { __float_as_uint(bv[nt].x),
                                       __float_as_uint(bv[nt].y) };
                    mma1688(acc[mt][nt], af, bb);
                }
            }
        }
        __syncthreads();
    }

    // Epilogue
    const int p0 = (cc < 2) ? 4 * cc : 4 * cc - 7;      // permuted pos of col 2cc
    const int p1 = (cc < 2) ? 4 * cc + 2 : 4 * cc - 5;  // permuted pos of col 2cc+1
#pragma unroll
    for (int mt = 0; mt < 4; ++mt) {
        const int row0 = rowBase + wr * 64 + mt * 16 + q;
#pragma unroll
        for (int nt = 0; nt < 4; ++nt) {
            const int grp = colBase + wc * 32 + nt * 8;   // 8-group base column
            if (mode == 0) {
                *reinterpret_cast<float2*>(&C[(size_t)row0 * N + grp + 2 * cc]) =
                    make_float2(acc[mt][nt][0], acc[mt][nt][1]);
                *reinterpret_cast<float2*>(&C[(size_t)(row0 + 8) * N + grp + 2 * cc]) =
                    make_float2(acc[mt][nt][2], acc[mt][nt][3]);
            } else if (grp < 2048) {
                // Q/K region: tf32-rounded, pair-permuted
                C[(size_t)row0 * N + grp + p0]       = to_tf32(acc[mt][nt][0]);
                C[(size_t)row0 * N + grp + p1]       = to_tf32(acc[mt][nt][1]);
                C[(size_t)(row0 + 8) * N + grp + p0] = to_tf32(acc[mt][nt][2]);
                C[(size_t)(row0 + 8) * N + grp + p1] = to_tf32(acc[mt][nt][3]);
            } else {
                // V region: fp16 transposed [b][h][d][t]
                const int dg = grp - 2048 + 2 * cc;       // global d index (0..1023)
                const int h = dg >> 6, d = dg & 63;
                const int b0r = row0 >> 11, t0 = row0 & 2047;
                __half* vb = vh + ((size_t)(b0r * NHEADS + h) * DHEAD) * SEQ;
                vb[(size_t)d * SEQ + t0]           = __float2half(acc[mt][nt][0]);
                vb[(size_t)(d + 1) * SEQ + t0]     = __float2half(acc[mt][nt][1]);
                vb[(size_t)d * SEQ + t0 + 8]       = __float2half(acc[mt][nt][2]);
                vb[(size_t)(d + 1) * SEQ + t0 + 8] = __float2half(acc[mt][nt][3]);
            }
        }
    }
}

// ---------------------------------------------------------------------------
// Pre-passes
// ---------------------------------------------------------------------------
// tf32-round + pair-permute each 8-col group: [c0..c7] -> [c0,c4,c1,c5,c2,c6,c3,c7]
__global__ void __launch_bounds__(256) cvt_perm_kernel(
    const float4* __restrict__ in, float4* __restrict__ out, int ngrp)
{
    int g = blockIdx.x * blockDim.x + threadIdx.x;
    if (g < ngrp) {
        float4 a = in[2 * g], b = in[2 * g + 1];
        out[2 * g] = make_float4(to_tf32(a.x), to_tf32(b.x), to_tf32(a.y), to_tf32(b.y));
        out[2 * g + 1] = make_float4(to_tf32(a.z), to_tf32(b.z), to_tf32(a.w), to_tf32(b.w));
    }
}

// W[K][N] -> Wt[N][K], tf32, pair-permuted along K
__global__ void __launch_bounds__(256) transpose_perm_kernel(
    const float* __restrict__ W, float* __restrict__ Wt, int K, int N)
{
    __shared__ float t[32][33];
    const int n0 = blockIdx.x * 32, k0 = blockIdx.y * 32;
    const int tx = threadIdx.x, ty = threadIdx.y;   // 32 x 8
#pragma unroll
    for (int i = 0; i < 4; ++i)
        t[ty + i * 8][tx] = W[(size_t)(k0 + ty + i * 8) * N + n0 + tx];
    __syncthreads();
    const int kperm = k0 + (tx & ~7) + permpos(tx & 7);
#pragma unroll
    for (int i = 0; i < 4; ++i)
        Wt[(size_t)(n0 + ty + i * 8) * K + kperm] = to_tf32(t[tx][ty + i * 8]);
}

// ---------------------------------------------------------------------------
// Tensor-core causal flash attention (tf32 QK^T + fp16 PV).
// Grid (16 q-tiles x 128, 16 heads, 4 batch), 256 threads = 8 warps.
// K tiles: 64x64 tf32 (pair-permuted), stride 68 floats. V tiles: fp16 V^T
// [64 d][64 t], stride 72 halves (conflict-free). P never touches SMEM:
// S c-frags convert in-register to fp16 a-frags (m16n8k16).
// ---------------------------------------------------------------------------
#define KSTR 68
#define KBUF (64 * KSTR)              // floats per K buffer
#define VSTR 72
#define VBUF (64 * VSTR)              // halves per V buffer
#define VOFF (2 * KBUF * 4)           // byte offset of V region
#define ATTN_SMEM (VOFF + 2 * VBUF * 2)   // 34816 + 18432 = 53248 bytes

__global__ void __launch_bounds__(256) attn_mma_kernel(
    const float* __restrict__ qkv, const __half* __restrict__ vh,
    float* __restrict__ out)
{
    extern __shared__ float sm[];
    __half* Vsm = reinterpret_cast<__half*>(reinterpret_cast<char*>(sm) + VOFF);

    const int tid = threadIdx.x, wq = tid >> 5, lane = tid & 31;
    const int q = lane >> 2, cc = lane & 3;
    const int rt = blockIdx.x, h = blockIdx.y, b = blockIdx.z;
    const int qb = rt * 128;
    const int nkt = 2 * rt + 2;
    const float* base = qkv + (size_t)b * SEQ * QKVCOLS;
    const __half* vbase = vh + ((size_t)(b * NHEADS + h) * DHEAD) * SEQ;
    const uint32_t smb = smem_u32(sm);

    // Resident Q a-frags, pre-scaled by 1/8. Permuted layout: cols (cc, cc+4)
    // of group ks live at 8ks+2cc, 8ks+2cc+1 -> float2 global loads.
    uint32_t aq[8][4];
    {
        const int r0 = qb + wq * 16 + q;
#pragma unroll
        for (int ks = 0; ks < 8; ++ks) {
            float2 fa = *reinterpret_cast<const float2*>(
                &base[(size_t)r0 * QKVCOLS + h * DHEAD + 8 * ks + 2 * cc]);
            float2 fb = *reinterpret_cast<const float2*>(
                &base[(size_t)(r0 + 8) * QKVCOLS + h * DHEAD + 8 * ks + 2 * cc]);
            aq[ks][0] = __float_as_uint(0.125f * fa.x);
            aq[ks][1] = __float_as_uint(0.125f * fb.x);
            aq[ks][2] = __float_as_uint(0.125f * fa.y);
            aq[ks][3] = __float_as_uint(0.125f * fb.y);
        }
    }

    float oacc[8][4];
#pragma unroll
    for (int nt = 0; nt < 8; ++nt)
#pragma unroll
        for (int e = 0; e < 4; ++e) oacc[nt][e] = 0.0f;
    float m0 = -INFINITY, m1 = -INFINITY, l0 = 0.0f, l1 = 0.0f;

    auto cptile = [&](int kt, int bufsel) {
        // K: 64 rows x 64 floats (permuted), stride KSTR
        const float* kS = base + (size_t)(kt * 64) * QKVCOLS + DMODEL + h * DHEAD;
        const uint32_t kD = smb + (uint32_t)bufsel * KBUF * 4;
#pragma unroll
        for (int i = 0; i < 4; ++i) {
            const int ch  = tid + i * 256;
            const int row = ch >> 4;
            const int c4  = (ch & 15) << 2;
            CP_ASYNC16(kD + (row * KSTR + c4) * 4, kS + (size_t)row * QKVCOLS + c4);
        }
        // V^T: 64 d-rows x 64 halves, stride VSTR
        const __half* vS = vbase + kt * 64;
        const uint32_t vD = smb + VOFF + (uint32_t)bufsel * VBUF * 2;
#pragma unroll
        for (int i = 0; i < 2; ++i) {
            const int ch = tid + i * 256;
            const int d  = ch >> 3;
            const int c8 = (ch & 7) << 3;
            CP_ASYNC16(vD + (d * VSTR + c8) * 2, vS + (size_t)d * SEQ + c8);
        }
        CP_COMMIT();
    };

    cptile(0, 0);

    for (int kt = 0; kt < nkt; ++kt) {
        const int buf = kt & 1;
        if (kt + 1 < nkt) { cptile(kt + 1, (kt + 1) & 1); CP_WAIT_1(); }
        else              { CP_WAIT_0(); }
        __syncthreads();

        const float*  Kb = sm + buf * KBUF;
        const __half* Vb = Vsm + buf * VBUF;

        // ---- S = (Q/8) K^T (tf32) ----
        float sacc[8][4];
#pragma unroll
        for (int nt = 0; nt < 8; ++nt) {
            sacc[nt][0] = sacc[nt][1] = sacc[nt][2] = sacc[nt][3] = 0.0f;
#pragma unroll
            for (int ks = 0; ks < 8; ++ks) {
                float2 kv = *reinterpret_cast<const float2*>(
                    &Kb[(8 * nt + q) * KSTR + 8 * ks + 2 * cc]);
                uint32_t bb[2] = { __float_as_uint(kv.x), __float_as_uint(kv.y) };
                mma1688(sacc[nt], aq[ks], bb);
            }
        }

        // ---- causal mask (diagonal region only) ----
        if (kt * 64 + 63 > qb + wq * 16) {
            const int r0g = qb + wq * 16 + q, r1g = r0g + 8;
#pragma unroll
            for (int nt = 0; nt < 8; ++nt) {
                const int c0g = kt * 64 + 8 * nt + 2 * cc;
                if (c0g     > r0g) sacc[nt][0] = -INFINITY;
                if (c0g + 1 > r0g) sacc[nt][1] = -INFINITY;
                if (c0g     > r1g) sacc[nt][2] = -INFINITY;
                if (c0g + 1 > r1g) sacc[nt][3] = -INFINITY;
            }
        }

        // ---- online softmax; P converted to fp16 a-frags in registers ----
        float cm0 = -INFINITY, cm1 = -INFINITY;
#pragma unroll
        for (int nt = 0; nt < 8; ++nt) {
            cm0 = fmaxf(cm0, fmaxf(sacc[nt][0], sacc[nt][1]));
            cm1 = fmaxf(cm1, fmaxf(sacc[nt][2], sacc[nt][3]));
        }
        cm0 = fmaxf(cm0, __shfl_xor_sync(0xffffffffu, cm0, 1));
        cm0 = fmaxf(cm0, __shfl_xor_sync(0xffffffffu, cm0, 2));
        cm1 = fmaxf(cm1, __shfl_xor_sync(0xffffffffu, cm1, 1));
        cm1 = fmaxf(cm1, __shfl_xor_sync(0xffffffffu, cm1, 2));

        const float mn0 = fmaxf(m0, cm0), mn1 = fmaxf(m1, cm1);
        const float corr0 = __expf(m0 - mn0), corr1 = __expf(m1 - mn1);

        uint32_t ph[8][2];
        float ps0 = 0.0f, ps1 = 0.0f;
#pragma unroll
        for (int nt = 0; nt < 8; ++nt) {
            const float pp0 = __expf(sacc[nt][0] - mn0);
            const float pp1 = __expf(sacc[nt][1] - mn0);
            const float pp2 = __expf(sacc[nt][2] - mn1);
            const float pp3 = __expf(sacc[nt][3] - mn1);
            ps0 += pp0 + pp1; ps1 += pp2 + pp3;
            ph[nt][0] = pack_h2(pp0, pp1);
            ph[nt][1] = pack_h2(pp2, pp3);
            oacc[nt][0] *= corr0; oacc[nt][1] *= corr0;
            oacc[nt][2] *= corr1; oacc[nt][3] *= corr1;
        }
        l0 = l0 * corr0 + ps0;
        l1 = l1 * corr1 + ps1;
        m0 = mn0; m1 = mn1;

        // ---- O += P V  (fp16 m16n8k16; a-frags straight from ph) ----
#pragma unroll
        for (int g = 0; g < 4; ++g) {
            uint32_t ap[4] = { ph[2 * g][0], ph[2 * g][1],
                               ph[2 * g + 1][0], ph[2 * g + 1][1] };
#pragma unroll
            for (int nt = 0; nt < 8; ++nt) {
                const __half* vrow = &Vb[(8 * nt + q) * VSTR + 16 * g + 2 * cc];
                uint32_t b0 = *reinterpret_cast<const uint32_t*>(vrow);
                uint32_t b1 = *reinterpret_cast<const uint32_t*>(vrow + 8);
                mma16816h(oacc[nt], ap, b0, b1);
            }
        }
        __syncthreads();   // everyone done with buf before refill
    }

    // ---- epilogue: reduce l over quad, normalize, tf32-round, permuted store ----
    l0 += __shfl_xor_sync(0xffffffffu, l0, 1);
    l0 += __shfl_xor_sync(0xffffffffu, l0, 2);
    l1 += __shfl_xor_sync(0xffffffffu, l1, 1);
    l1 += __shfl_xor_sync(0xffffffffu, l1, 2);
    const float inv0 = 1.0f / l0, inv1 = 1.0f / l1;

    const int p0 = (cc < 2) ? 4 * cc : 4 * cc - 7;
    const int p1 = (cc < 2) ? 4 * cc + 2 : 4 * cc - 5;
    float* ob = out + (size_t)(b * SEQ + qb + wq * 16 + q) * DMODEL + h * DHEAD;
#pragma unroll
    for (int nt = 0; nt < 8; ++nt) {
        ob[8 * nt + p0] = to_tf32(oacc[nt][0] * inv0);
        ob[8 * nt + p1] = to_tf32(oacc[nt][1] * inv0);
        ob[(size_t)8 * DMODEL + 8 * nt + p0] = to_tf32(oacc[nt][2] * inv1);
        ob[(size_t)8 * DMODEL + 8 * nt + p1] = to_tf32(oacc[nt][3] * inv1);
    }
}

// ---------------------------------------------------------------------------
extern "C" void kernel_launch(void* const* d_in, const int* in_sizes, int n_in,
                              void* d_out, int out_size)
{
    const float* x     = (const float*)d_in[0];
    const float* W_qkv = (const float*)d_in[1];
    const float* W_out = (const float*)d_in[2];
    float* out = (float*)d_out;

    float *xc, *qkv, *attn, *wqkvT, *woutT;
    __half* vh;
    cudaGetSymbolAddress((void**)&xc,    g_xc);
    cudaGetSymbolAddress((void**)&qkv,   g_qkv);
    cudaGetSymbolAddress((void**)&attn,  g_attn);
    cudaGetSymbolAddress((void**)&wqkvT, g_wqkvT);
    cudaGetSymbolAddress((void**)&woutT, g_woutT);
    cudaGetSymbolAddress((void**)&vh,    g_vh);

    cudaFuncSetAttribute(gemm_tf32_kernel,
                         cudaFuncAttributeMaxDynamicSharedMemorySize, GEMM_SMEM);
    cudaFuncSetAttribute(attn_mma_kernel,
                         cudaFuncAttributeMaxDynamicSharedMemorySize, ATTN_SMEM);

    // Pre-passes (tf32 round + pair-permute along K)
    const int ngrp = MROWS * DMODEL / 8;
    cvt_perm_kernel<<<ngrp / 256, 256>>>((const float4*)x, (float4*)xc, ngrp);
    transpose_perm_kernel<<<dim3(QKVCOLS / 32, DMODEL / 32), dim3(32, 8)>>>(
        W_qkv, wqkvT, DMODEL, QKVCOLS);
    transpose_perm_kernel<<<dim3(DMODEL / 32, DMODEL / 32), dim3(32, 8)>>>(
        W_out, woutT, DMODEL, DMODEL);

    // 1) QKV projection; epilogue emits permuted tf32 Q/K + fp16 V^T
    gemm_tf32_kernel<<<dim3(QKVCOLS / 128, MROWS / 128), 256, GEMM_SMEM>>>(
        xc, wqkvT, qkv, vh, MROWS, QKVCOLS, DMODEL, 1);

    // 2) Flash attention (tf32 QK^T, fp16 PV)
    attn_mma_kernel<<<dim3(SEQ / 128, NHEADS, BSZ), 256, ATTN_SMEM>>>(qkv, vh, attn);

    // 3) Output projection -> plain f32 result
    gemm_tf32_kernel<<<dim3(DMODEL / 128, MROWS / 128), 256, GEMM_SMEM>>>(
        attn, woutT, out, vh, MROWS, DMODEL, DMODEL, 0);
}

// round 7
// speedup vs baseline: 5.5453x; 1.2728x over previous
#include <cuda_runtime.h>
#include <cuda_fp16.h>
#include <cstdint>
#include <math.h>

// Problem constants
#define BSZ 4
#define SEQ 2048
#define DMODEL 1024
#define NHEADS 16
#define DHEAD 64
#define QKVCOLS (3 * DMODEL)          // 3072
#define MROWS (BSZ * SEQ)             // 8192

// Scratch (device globals)
__device__ float  g_xc   [(size_t)MROWS * DMODEL];    // x, tf32
__device__ float  g_qkv  [(size_t)MROWS * QKVCOLS];   // Q,K tf32 (V region unused)
__device__ float  g_attn [(size_t)MROWS * DMODEL];    // attn out, tf32
__device__ float  g_wqkvT[(size_t)QKVCOLS * DMODEL];  // W_qkv^T, tf32
__device__ float  g_woutT[(size_t)DMODEL * DMODEL];   // W_out^T, tf32
__device__ __half g_vh   [(size_t)BSZ * NHEADS * DHEAD * SEQ];  // V^T fp16 [b][h][d][t]

// ---------------------------------------------------------------------------
// Helpers
// ---------------------------------------------------------------------------
__device__ __forceinline__ float to_tf32(float x) {
    uint32_t u; asm("cvt.rna.tf32.f32 %0, %1;" : "=r"(u) : "f"(x));
    return __uint_as_float(u);
}
__device__ __forceinline__ uint32_t smem_u32(const void* p) {
    uint32_t a;
    asm("{ .reg .u64 t; cvta.to.shared.u64 t, %1; cvt.u32.u64 %0, t; }"
        : "=r"(a) : "l"(p));
    return a;
}
__device__ __forceinline__ uint32_t pack_h2(float a, float b) {
    __half2 h = __floats2half2_rn(a, b);
    return *reinterpret_cast<uint32_t*>(&h);
}

#define CP_ASYNC16(dst_u32, src_ptr) \
    asm volatile("cp.async.ca.shared.global [%0], [%1], 16;" \
                 :: "r"(dst_u32), "l"(src_ptr) : "memory")
#define CP_COMMIT() asm volatile("cp.async.commit_group;" ::: "memory")
#define CP_WAIT_1() asm volatile("cp.async.wait_group 1;" ::: "memory")
#define CP_WAIT_0() asm volatile("cp.async.wait_group 0;" ::: "memory")

// ldmatrix x4: four 8x8 b16 tiles (= four 8x4 fp32 tiles). Lane i of each
// 8-lane group supplies the row address of its tile; result reg j = tile j,
// lane -> (row lane/4, 32-bit col lane%4) == the mma fragment layout.
__device__ __forceinline__ void ldm_x4(uint32_t* r, uint32_t addr) {
    asm volatile("ldmatrix.sync.aligned.m8n8.x4.shared.b16 {%0,%1,%2,%3}, [%4];"
        : "=r"(r[0]), "=r"(r[1]), "=r"(r[2]), "=r"(r[3]) : "r"(addr));
}

// tf32 m16n8k8
__device__ __forceinline__ void mma1688(float* d, const uint32_t* a, const uint32_t* b) {
    asm volatile(
        "mma.sync.aligned.m16n8k8.row.col.f32.tf32.tf32.f32 "
        "{%0,%1,%2,%3}, {%4,%5,%6,%7}, {%8,%9}, {%0,%1,%2,%3};"
        : "+f"(d[0]), "+f"(d[1]), "+f"(d[2]), "+f"(d[3])
        : "r"(a[0]), "r"(a[1]), "r"(a[2]), "r"(a[3]), "r"(b[0]), "r"(b[1]));
}
// fp16 m16n8k16, f32 accumulate
__device__ __forceinline__ void mma16816h(float* d, const uint32_t* a,
                                          uint32_t b0, uint32_t b1) {
    asm volatile(
        "mma.sync.aligned.m16n8k16.row.col.f32.f16.f16.f32 "
        "{%0,%1,%2,%3}, {%4,%5,%6,%7}, {%8,%9}, {%0,%1,%2,%3};"
        : "+f"(d[0]), "+f"(d[1]), "+f"(d[2]), "+f"(d[3])
        : "r"(a[0]), "r"(a[1]), "r"(a[2]), "r"(a[3]), "r"(b0), "r"(b1));
}

#define GEMM_SMEM 73728

// ---------------------------------------------------------------------------
// tf32 GEMM: C[M,N] = A[M,K] * Bt[N,K]^T. 128x128 CTA tiles, BK=32, cp.async
// double buffer, 8 warps 64x32. All fragments via ldmatrix.x4.
// mode 0: plain f32 out. mode 1: QKV (cols<2048 -> tf32 Q/K; >=2048 -> fp16 V^T).
// ---------------------------------------------------------------------------
__global__ void __launch_bounds__(256) gemm_tf32_kernel(
    const float* __restrict__ A, const float* __restrict__ Bt,
    float* __restrict__ C, __half* __restrict__ vh,
    int M, int N, int K, int mode)
{
    extern __shared__ char smem[];
    const int tid = threadIdx.x, wid = tid >> 5, lane = tid & 31;
    const int rowBase = blockIdx.y << 7, colBase = blockIdx.x << 7;
    const uint32_t sb = smem_u32(smem);

    const int wr = wid >> 2, wc = wid & 3;
    const int q = lane >> 2, cc = lane & 3;

    // ldmatrix per-lane row/col offsets
    const int arow = (lane & 7) + ((lane >> 3) & 1) * 8;   // A: tiles {r,r+8}x{k,k+4}
    const int acol = (lane >> 4) * 4;
    const int brow = (lane & 7) + (lane >> 4) * 8;         // B: {n,n+8} x {k,k+4}
    const int bcol = ((lane >> 3) & 1) * 4;

    float acc[4][4][4];
#pragma unroll
    for (int a = 0; a < 4; ++a)
#pragma unroll
        for (int b = 0; b < 4; ++b)
#pragma unroll
            for (int r = 0; r < 4; ++r) acc[a][b][r] = 0.0f;

    const int nchunks = K >> 5;

    auto load_tile = [&](int c, int buf) {
        const int k0 = c << 5;
#pragma unroll
        for (int i = 0; i < 4; ++i) {
            const int f   = tid + i * 256;
            const int row = f >> 3;
            const int c4  = (f & 7) << 2;
            CP_ASYNC16(sb + (buf * 18432) + (row * 36 + c4) * 4,
                       &A[(size_t)(rowBase + row) * K + k0 + c4]);
            CP_ASYNC16(sb + 36864 + (buf * 18432) + (row * 36 + c4) * 4,
                       &Bt[(size_t)(colBase + row) * K + k0 + c4]);
        }
        CP_COMMIT();
    };

    load_tile(0, 0);

    for (int c = 0; c < nchunks; ++c) {
        const int buf = c & 1;
        if (c + 1 < nchunks) { load_tile(c + 1, (c + 1) & 1); CP_WAIT_1(); }
        else                 { CP_WAIT_0(); }
        __syncthreads();

        const uint32_t aAddr = sb + buf * 18432
                             + ((wr * 64 + arow) * 36 + acol) * 4;
        const uint32_t bAddr = sb + 36864 + buf * 18432
                             + ((wc * 32 + brow) * 36 + bcol) * 4;

#pragma unroll
        for (int ks = 0; ks < 4; ++ks) {
            uint32_t bfr[2][4];
#pragma unroll
            for (int h = 0; h < 2; ++h)
                ldm_x4(bfr[h], bAddr + (h * 16 * 36 + ks * 8) * 4);
#pragma unroll
            for (int mt = 0; mt < 4; ++mt) {
                uint32_t af[4];
                ldm_x4(af, aAddr + (mt * 16 * 36 + ks * 8) * 4);
#pragma unroll
                for (int h = 0; h < 2; ++h) {
                    mma1688(acc[mt][2 * h],     af, &bfr[h][0]);
                    mma1688(acc[mt][2 * h + 1], af, &bfr[h][2]);
                }
            }
        }
        __syncthreads();
    }

    // Epilogue
#pragma unroll
    for (int mt = 0; mt < 4; ++mt) {
        const int row0 = rowBase + wr * 64 + mt * 16 + q;
#pragma unroll
        for (int nt = 0; nt < 4; ++nt) {
            const int grp = colBase + wc * 32 + nt * 8;
            if (mode == 0) {
                *reinterpret_cast<float2*>(&C[(size_t)row0 * N + grp + 2 * cc]) =
                    make_float2(acc[mt][nt][0], acc[mt][nt][1]);
                *reinterpret_cast<float2*>(&C[(size_t)(row0 + 8) * N + grp + 2 * cc]) =
                    make_float2(acc[mt][nt][2], acc[mt][nt][3]);
            } else if (grp < 2048) {
                *reinterpret_cast<float2*>(&C[(size_t)row0 * N + grp + 2 * cc]) =
                    make_float2(to_tf32(acc[mt][nt][0]), to_tf32(acc[mt][nt][1]));
                *reinterpret_cast<float2*>(&C[(size_t)(row0 + 8) * N + grp + 2 * cc]) =
                    make_float2(to_tf32(acc[mt][nt][2]), to_tf32(acc[mt][nt][3]));
            } else {
                // V region: fp16 transposed [b][h][d][t]
                const int dg = grp - 2048 + 2 * cc;
                const int h = dg >> 6, d = dg & 63;
                const int b0r = row0 >> 11, t0 = row0 & 2047;
                __half* vb = vh + ((size_t)(b0r * NHEADS + h) * DHEAD) * SEQ;
                vb[(size_t)d * SEQ + t0]           = __float2half(acc[mt][nt][0]);
                vb[(size_t)(d + 1) * SEQ + t0]     = __float2half(acc[mt][nt][1]);
                vb[(size_t)d * SEQ + t0 + 8]       = __float2half(acc[mt][nt][2]);
                vb[(size_t)(d + 1) * SEQ + t0 + 8] = __float2half(acc[mt][nt][3]);
            }
        }
    }
}

// ---------------------------------------------------------------------------
// Pre-passes
// ---------------------------------------------------------------------------
__global__ void __launch_bounds__(256) cvt_tf32_kernel(
    const float4* __restrict__ in, float4* __restrict__ out, int n4)
{
    int i = blockIdx.x * blockDim.x + threadIdx.x;
    if (i < n4) {
        float4 v = in[i];
        v.x = to_tf32(v.x); v.y = to_tf32(v.y);
        v.z = to_tf32(v.z); v.w = to_tf32(v.w);
        out[i] = v;
    }
}

__global__ void __launch_bounds__(256) transpose_tf32_kernel(
    const float* __restrict__ W, float* __restrict__ Wt, int K, int N)
{
    __shared__ float t[32][33];
    const int n0 = blockIdx.x * 32, k0 = blockIdx.y * 32;
    const int tx = threadIdx.x, ty = threadIdx.y;   // 32 x 8
#pragma unroll
    for (int i = 0; i < 4; ++i)
        t[ty + i * 8][tx] = W[(size_t)(k0 + ty + i * 8) * N + n0 + tx];
    __syncthreads();
#pragma unroll
    for (int i = 0; i < 4; ++i)
        Wt[(size_t)(n0 + ty + i * 8) * K + k0 + tx] = to_tf32(t[tx][ty + i * 8]);
}

// ---------------------------------------------------------------------------
// Tensor-core causal flash attention (tf32 QK^T + fp16 PV, ldmatrix frags).
// Grid (16 q-tiles x 128, 16 heads, 4 batch), 256 threads = 8 warps.
// ---------------------------------------------------------------------------
#define KSTR 68
#define KBUF (64 * KSTR)              // floats per K buffer
#define VSTR 72
#define VBUF (64 * VSTR)              // halves per V buffer
#define VOFF (2 * KBUF * 4)           // byte offset of V region
#define ATTN_SMEM (VOFF + 2 * VBUF * 2)   // 53248 bytes

__global__ void __launch_bounds__(256) attn_mma_kernel(
    const float* __restrict__ qkv, const __half* __restrict__ vh,
    float* __restrict__ out)
{
    extern __shared__ float sm[];

    const int tid = threadIdx.x, wq = tid >> 5, lane = tid & 31;
    const int q = lane >> 2, cc = lane & 3;
    const int rt = blockIdx.x, h = blockIdx.y, b = blockIdx.z;
    const int qb = rt * 128;
    const int nkt = 2 * rt + 2;
    const float* base = qkv + (size_t)b * SEQ * QKVCOLS;
    const __half* vbase = vh + ((size_t)(b * NHEADS + h) * DHEAD) * SEQ;
    const uint32_t smb = smem_u32(sm);

    // ldmatrix per-lane offsets (b-frag pattern)
    const int brow = (lane & 7) + (lane >> 4) * 8;
    const int bcol = ((lane >> 3) & 1) * 4;
    const int vrow = (lane & 7) + (lane >> 4) * 8;
    const int vcol = ((lane >> 3) & 1) * 8;     // halves

    // Resident Q a-frags, pre-scaled by 1/8 (exact)
    uint32_t aq[8][4];
    {
        const int r0 = qb + wq * 16 + q;
#pragma unroll
        for (int ks = 0; ks < 8; ++ks)
#pragma unroll
            for (int e = 0; e < 4; ++e) {
                const int row = r0 + (e & 1) * 8;
                const int col = h * DHEAD + 8 * ks + cc + (e >> 1) * 4;
                aq[ks][e] = __float_as_uint(
                    0.125f * base[(size_t)row * QKVCOLS + col]);
            }
    }

    float oacc[8][4];
#pragma unroll
    for (int nt = 0; nt < 8; ++nt)
#pragma unroll
        for (int e = 0; e < 4; ++e) oacc[nt][e] = 0.0f;
    float m0 = -INFINITY, m1 = -INFINITY, l0 = 0.0f, l1 = 0.0f;

    auto cptile = [&](int kt, int bufsel) {
        const float* kS = base + (size_t)(kt * 64) * QKVCOLS + DMODEL + h * DHEAD;
        const uint32_t kD = smb + (uint32_t)bufsel * KBUF * 4;
#pragma unroll
        for (int i = 0; i < 4; ++i) {
            const int ch  = tid + i * 256;
            const int row = ch >> 4;
            const int c4  = (ch & 15) << 2;
            CP_ASYNC16(kD + (row * KSTR + c4) * 4, kS + (size_t)row * QKVCOLS + c4);
        }
        const __half* vS = vbase + kt * 64;
        const uint32_t vD = smb + VOFF + (uint32_t)bufsel * VBUF * 2;
#pragma unroll
        for (int i = 0; i < 2; ++i) {
            const int ch = tid + i * 256;
            const int d  = ch >> 3;
            const int c8 = (ch & 7) << 3;
            CP_ASYNC16(vD + (d * VSTR + c8) * 2, vS + (size_t)d * SEQ + c8);
        }
        CP_COMMIT();
    };

    cptile(0, 0);

    for (int kt = 0; kt < nkt; ++kt) {
        const int buf = kt & 1;
        if (kt + 1 < nkt) { cptile(kt + 1, (kt + 1) & 1); CP_WAIT_1(); }
        else              { CP_WAIT_0(); }
        __syncthreads();

        const uint32_t kAddr = smb + (uint32_t)buf * KBUF * 4
                             + (brow * KSTR + bcol) * 4;
        const uint32_t vAddr = smb + VOFF + (uint32_t)buf * VBUF * 2
                             + (vrow * VSTR + vcol) * 2;

        // ---- S = (Q/8) K^T (tf32, ldmatrix b-frags) ----
        float sacc[8][4];
#pragma unroll
        for (int hh = 0; hh < 4; ++hh) {
            sacc[2*hh][0] = sacc[2*hh][1] = sacc[2*hh][2] = sacc[2*hh][3] = 0.0f;
            sacc[2*hh+1][0] = sacc[2*hh+1][1] = sacc[2*hh+1][2] = sacc[2*hh+1][3] = 0.0f;
#pragma unroll
            for (int ks = 0; ks < 8; ++ks) {
                uint32_t kb[4];
                ldm_x4(kb, kAddr + (hh * 16 * KSTR + ks * 8) * 4);
                mma1688(sacc[2 * hh],     aq[ks], &kb[0]);
                mma1688(sacc[2 * hh + 1], aq[ks], &kb[2]);
            }
        }

        // ---- causal mask (diagonal region only) ----
        if (kt * 64 + 63 > qb + wq * 16) {
            const int r0g = qb + wq * 16 + q, r1g = r0g + 8;
#pragma unroll
            for (int nt = 0; nt < 8; ++nt) {
                const int c0g = kt * 64 + 8 * nt + 2 * cc;
                if (c0g     > r0g) sacc[nt][0] = -INFINITY;
                if (c0g + 1 > r0g) sacc[nt][1] = -INFINITY;
                if (c0g     > r1g) sacc[nt][2] = -INFINITY;
                if (c0g + 1 > r1g) sacc[nt][3] = -INFINITY;
            }
        }

        // ---- online softmax; P -> fp16 a-frags in registers ----
        float cm0 = -INFINITY, cm1 = -INFINITY;
#pragma unroll
        for (int nt = 0; nt < 8; ++nt) {
            cm0 = fmaxf(cm0, fmaxf(sacc[nt][0], sacc[nt][1]));
            cm1 = fmaxf(cm1, fmaxf(sacc[nt][2], sacc[nt][3]));
        }
        cm0 = fmaxf(cm0, __shfl_xor_sync(0xffffffffu, cm0, 1));
        cm0 = fmaxf(cm0, __shfl_xor_sync(0xffffffffu, cm0, 2));
        cm1 = fmaxf(cm1, __shfl_xor_sync(0xffffffffu, cm1, 1));
        cm1 = fmaxf(cm1, __shfl_xor_sync(0xffffffffu, cm1, 2));

        const float mn0 = fmaxf(m0, cm0), mn1 = fmaxf(m1, cm1);
        const float corr0 = __expf(m0 - mn0), corr1 = __expf(m1 - mn1);

        uint32_t ph[8][2];
        float ps0 = 0.0f, ps1 = 0.0f;
#pragma unroll
        for (int nt = 0; nt < 8; ++nt) {
            const float pp0 = __expf(sacc[nt][0] - mn0);
            const float pp1 = __expf(sacc[nt][1] - mn0);
            const float pp2 = __expf(sacc[nt][2] - mn1);
            const float pp3 = __expf(sacc[nt][3] - mn1);
            ps0 += pp0 + pp1; ps1 += pp2 + pp3;
            ph[nt][0] = pack_h2(pp0, pp1);
            ph[nt][1] = pack_h2(pp2, pp3);
            oacc[nt][0] *= corr0; oacc[nt][1] *= corr0;
            oacc[nt][2] *= corr1; oacc[nt][3] *= corr1;
        }
        l0 = l0 * corr0 + ps0;
        l1 = l1 * corr1 + ps1;
        m0 = mn0; m1 = mn1;

        // ---- O += P V (fp16 m16n8k16, ldmatrix V b-frags) ----
#pragma unroll
        for (int g = 0; g < 4; ++g) {
            uint32_t ap[4] = { ph[2 * g][0], ph[2 * g][1],
                               ph[2 * g + 1][0], ph[2 * g + 1][1] };
#pragma unroll
            for (int hh = 0; hh < 4; ++hh) {
                uint32_t vb4[4];
                ldm_x4(vb4, vAddr + (hh * 16 * VSTR + g * 16) * 2);
                mma16816h(oacc[2 * hh],     ap, vb4[0], vb4[1]);
                mma16816h(oacc[2 * hh + 1], ap, vb4[2], vb4[3]);
            }
        }
        __syncthreads();   // everyone done with buf before refill
    }

    // ---- epilogue ----
    l0 += __shfl_xor_sync(0xffffffffu, l0, 1);
    l0 += __shfl_xor_sync(0xffffffffu, l0, 2);
    l1 += __shfl_xor_sync(0xffffffffu, l1, 1);
    l1 += __shfl_xor_sync(0xffffffffu, l1, 2);
    const float inv0 = 1.0f / l0, inv1 = 1.0f / l1;

    float* ob = out + (size_t)(b * SEQ + qb + wq * 16 + q) * DMODEL + h * DHEAD;
#pragma unroll
    for (int nt = 0; nt < 8; ++nt) {
        *reinterpret_cast<float2*>(&ob[8 * nt + 2 * cc]) =
            make_float2(to_tf32(oacc[nt][0] * inv0), to_tf32(oacc[nt][1] * inv0));
        *reinterpret_cast<float2*>(&ob[(size_t)8 * DMODEL + 8 * nt + 2 * cc]) =
            make_float2(to_tf32(oacc[nt][2] * inv1), to_tf32(oacc[nt][3] * inv1));
    }
}

// ---------------------------------------------------------------------------
extern "C" void kernel_launch(void* const* d_in, const int* in_sizes, int n_in,
                              void* d_out, int out_size)
{
    const float* x     = (const float*)d_in[0];
    const float* W_qkv = (const float*)d_in[1];
    const float* W_out = (const float*)d_in[2];
    float* out = (float*)d_out;

    float *xc, *qkv, *attn, *wqkvT, *woutT;
    __half* vh;
    cudaGetSymbolAddress((void**)&xc,    g_xc);
    cudaGetSymbolAddress((void**)&qkv,   g_qkv);
    cudaGetSymbolAddress((void**)&attn,  g_attn);
    cudaGetSymbolAddress((void**)&wqkvT, g_wqkvT);
    cudaGetSymbolAddress((void**)&woutT, g_woutT);
    cudaGetSymbolAddress((void**)&vh,    g_vh);

    cudaFuncSetAttribute(gemm_tf32_kernel,
                         cudaFuncAttributeMaxDynamicSharedMemorySize, GEMM_SMEM);
    cudaFuncSetAttribute(attn_mma_kernel,
                         cudaFuncAttributeMaxDynamicSharedMemorySize, ATTN_SMEM);

    // Pre-passes (tf32 rounding; weight transposes)
    const int n4 = MROWS * DMODEL / 4;
    cvt_tf32_kernel<<<n4 / 256, 256>>>((const float4*)x, (float4*)xc, n4);
    transpose_tf32_kernel<<<dim3(QKVCOLS / 32, DMODEL / 32), dim3(32, 8)>>>(
        W_qkv, wqkvT, DMODEL, QKVCOLS);
    transpose_tf32_kernel<<<dim3(DMODEL / 32, DMODEL / 32), dim3(32, 8)>>>(
        W_out, woutT, DMODEL, DMODEL);

    // 1) QKV projection; epilogue emits tf32 Q/K + fp16 V^T
    gemm_tf32_kernel<<<dim3(QKVCOLS / 128, MROWS / 128), 256, GEMM_SMEM>>>(
        xc, wqkvT, qkv, vh, MROWS, QKVCOLS, DMODEL, 1);

    // 2) Flash attention (tf32 QK^T, fp16 PV)
    attn_mma_kernel<<<dim3(SEQ / 128, NHEADS, BSZ), 256, ATTN_SMEM>>>(qkv, vh, attn);

    // 3) Output projection -> plain f32 result
    gemm_tf32_kernel<<<dim3(DMODEL / 128, MROWS / 128), 256, GEMM_SMEM>>>(
        attn, woutT, out, vh, MROWS, DMODEL, DMODEL, 0);
}

// round 8
// speedup vs baseline: 7.9500x; 1.4336x over previous
#include <cuda_runtime.h>
#include <cuda_fp16.h>
#include <cstdint>
#include <math.h>

// Problem constants
#define BSZ 4
#define SEQ 2048
#define DMODEL 1024
#define NHEADS 16
#define DHEAD 64
#define QKVCOLS (3 * DMODEL)          // 3072
#define MROWS (BSZ * SEQ)             // 8192

// Scratch (device globals)
__device__ __half g_xh    [(size_t)MROWS * DMODEL];    // x, fp16
__device__ float  g_qkv   [(size_t)MROWS * QKVCOLS];   // Q,K tf32 (V region unused)
__device__ __half g_attnh [(size_t)MROWS * DMODEL];    // attn out, fp16
__device__ __half g_wqkvTh[(size_t)QKVCOLS * DMODEL];  // W_qkv^T, fp16
__device__ __half g_woutTh[(size_t)DMODEL * DMODEL];   // W_out^T, fp16
__device__ __half g_vh    [(size_t)BSZ * NHEADS * DHEAD * SEQ]; // V^T fp16 [b][h][d][t]

// ---------------------------------------------------------------------------
// Helpers
// ---------------------------------------------------------------------------
__device__ __forceinline__ float to_tf32(float x) {
    uint32_t u; asm("cvt.rna.tf32.f32 %0, %1;" : "=r"(u) : "f"(x));
    return __uint_as_float(u);
}
__device__ __forceinline__ uint32_t smem_u32(const void* p) {
    uint32_t a;
    asm("{ .reg .u64 t; cvta.to.shared.u64 t, %1; cvt.u32.u64 %0, t; }"
        : "=r"(a) : "l"(p));
    return a;
}
__device__ __forceinline__ uint32_t pack_h2(float a, float b) {
    __half2 h = __floats2half2_rn(a, b);
    return *reinterpret_cast<uint32_t*>(&h);
}

#define CP_ASYNC16(dst_u32, src_ptr) \
    asm volatile("cp.async.ca.shared.global [%0], [%1], 16;" \
                 :: "r"(dst_u32), "l"(src_ptr) : "memory")
#define CP_COMMIT() asm volatile("cp.async.commit_group;" ::: "memory")
#define CP_WAIT_1() asm volatile("cp.async.wait_group 1;" ::: "memory")
#define CP_WAIT_0() asm volatile("cp.async.wait_group 0;" ::: "memory")

__device__ __forceinline__ void ldm_x4(uint32_t* r, uint32_t addr) {
    asm volatile("ldmatrix.sync.aligned.m8n8.x4.shared.b16 {%0,%1,%2,%3}, [%4];"
        : "=r"(r[0]), "=r"(r[1]), "=r"(r[2]), "=r"(r[3]) : "r"(addr));
}

// tf32 m16n8k8 (attention QK^T)
__device__ __forceinline__ void mma1688(float* d, const uint32_t* a, const uint32_t* b) {
    asm volatile(
        "mma.sync.aligned.m16n8k8.row.col.f32.tf32.tf32.f32 "
        "{%0,%1,%2,%3}, {%4,%5,%6,%7}, {%8,%9}, {%0,%1,%2,%3};"
        : "+f"(d[0]), "+f"(d[1]), "+f"(d[2]), "+f"(d[3])
        : "r"(a[0]), "r"(a[1]), "r"(a[2]), "r"(a[3]), "r"(b[0]), "r"(b[1]));
}
// fp16 m16n8k16, f32 accumulate
__device__ __forceinline__ void mma16816h(float* d, const uint32_t* a,
                                          uint32_t b0, uint32_t b1) {
    asm volatile(
        "mma.sync.aligned.m16n8k16.row.col.f32.f16.f16.f32 "
        "{%0,%1,%2,%3}, {%4,%5,%6,%7}, {%8,%9}, {%0,%1,%2,%3};"
        : "+f"(d[0]), "+f"(d[1]), "+f"(d[2]), "+f"(d[3])
        : "r"(a[0]), "r"(a[1]), "r"(a[2]), "r"(a[3]), "r"(b0), "r"(b1));
}

// ---------------------------------------------------------------------------
// fp16 GEMM: C[M,N] = A[M,K] * Bt[N,K]^T, f32 accumulate.
// 128x128 CTA tiles, BK=64, cp.async double buffer, 8 warps 64x32 each.
// SMEM rows stride 72 halves (144B) -> all ldmatrix phases conflict-free.
// mode 0: f32 out. mode 1: QKV (cols<2048 -> tf32 Q/K; >=2048 -> fp16 V^T).
// ---------------------------------------------------------------------------
#define GSTR 72
#define GBUF (128 * GSTR * 2)         // bytes per A (or B) buffer = 18432
#define GEMM_SMEM (4 * GBUF)          // 73728

__global__ void __launch_bounds__(256) gemm_fp16_kernel(
    const __half* __restrict__ A, const __half* __restrict__ Bt,
    float* __restrict__ C, __half* __restrict__ vh,
    int M, int N, int K, int mode)
{
    extern __shared__ char smem[];
    const int tid = threadIdx.x, wid = tid >> 5, lane = tid & 31;
    const int rowBase = blockIdx.y << 7, colBase = blockIdx.x << 7;
    const uint32_t sb = smem_u32(smem);

    const int wr = wid >> 2, wc = wid & 3;
    const int q = lane >> 2, cc = lane & 3;

    // ldmatrix per-lane offsets (halves)
    const int ar = (lane & 7) + ((lane >> 3) & 1) * 8;  // A: {r,r+8} x {k,k+8}
    const int ac = (lane >> 4) * 8;
    const int br = (lane & 7) + (lane >> 4) * 8;        // B: {n,n+8} x {k,k+8}
    const int bc = ((lane >> 3) & 1) * 8;

    float acc[4][4][4];
#pragma unroll
    for (int a = 0; a < 4; ++a)
#pragma unroll
        for (int b = 0; b < 4; ++b)
#pragma unroll
            for (int r = 0; r < 4; ++r) acc[a][b][r] = 0.0f;

    const int nchunks = K >> 6;

    auto load_tile = [&](int c, int buf) {
        const int k0 = c << 6;
#pragma unroll
        for (int i = 0; i < 4; ++i) {
            const int f   = tid + i * 256;
            const int row = f >> 3;            // 0..127
            const int c8  = (f & 7) << 3;      // halves, 16B steps
            CP_ASYNC16(sb + buf * GBUF + (row * GSTR + c8) * 2,
                       &A[(size_t)(rowBase + row) * K + k0 + c8]);
            CP_ASYNC16(sb + 2 * GBUF + buf * GBUF + (row * GSTR + c8) * 2,
                       &Bt[(size_t)(colBase + row) * K + k0 + c8]);
        }
        CP_COMMIT();
    };

    load_tile(0, 0);

    for (int c = 0; c < nchunks; ++c) {
        const int buf = c & 1;
        if (c + 1 < nchunks) { load_tile(c + 1, (c + 1) & 1); CP_WAIT_1(); }
        else                 { CP_WAIT_0(); }
        __syncthreads();

        const uint32_t aAddr = sb + buf * GBUF + ((wr * 64 + ar) * GSTR + ac) * 2;
        const uint32_t bAddr = sb + 2 * GBUF + buf * GBUF
                             + ((wc * 32 + br) * GSTR + bc) * 2;

#pragma unroll
        for (int ks = 0; ks < 4; ++ks) {       // 16-deep k-steps
            uint32_t bfr[2][4];
#pragma unroll
            for (int nh = 0; nh < 2; ++nh)
                ldm_x4(bfr[nh], bAddr + (nh * 16 * GSTR + ks * 16) * 2);
#pragma unroll
            for (int mt = 0; mt < 4; ++mt) {
                uint32_t af[4];
                ldm_x4(af, aAddr + (mt * 16 * GSTR + ks * 16) * 2);
#pragma unroll
                for (int nh = 0; nh < 2; ++nh) {
                    mma16816h(acc[mt][2 * nh],     af, bfr[nh][0], bfr[nh][1]);
                    mma16816h(acc[mt][2 * nh + 1], af, bfr[nh][2], bfr[nh][3]);
                }
            }
        }
        __syncthreads();
    }

    // Epilogue
#pragma unroll
    for (int mt = 0; mt < 4; ++mt) {
        const int row0 = rowBase + wr * 64 + mt * 16 + q;
#pragma unroll
        for (int nt = 0; nt < 4; ++nt) {
            const int grp = colBase + wc * 32 + nt * 8;
            if (mode == 0) {
                *reinterpret_cast<float2*>(&C[(size_t)row0 * N + grp + 2 * cc]) =
                    make_float2(acc[mt][nt][0], acc[mt][nt][1]);
                *reinterpret_cast<float2*>(&C[(size_t)(row0 + 8) * N + grp + 2 * cc]) =
                    make_float2(acc[mt][nt][2], acc[mt][nt][3]);
            } else if (grp < 2048) {
                *reinterpret_cast<float2*>(&C[(size_t)row0 * N + grp + 2 * cc]) =
                    make_float2(to_tf32(acc[mt][nt][0]), to_tf32(acc[mt][nt][1]));
                *reinterpret_cast<float2*>(&C[(size_t)(row0 + 8) * N + grp + 2 * cc]) =
                    make_float2(to_tf32(acc[mt][nt][2]), to_tf32(acc[mt][nt][3]));
            } else {
                const int dg = grp - 2048 + 2 * cc;
                const int h = dg >> 6, d = dg & 63;
                const int b0r = row0 >> 11, t0 = row0 & 2047;
                __half* vb = vh + ((size_t)(b0r * NHEADS + h) * DHEAD) * SEQ;
                vb[(size_t)d * SEQ + t0]           = __float2half(acc[mt][nt][0]);
                vb[(size_t)(d + 1) * SEQ + t0]     = __float2half(acc[mt][nt][1]);
                vb[(size_t)d * SEQ + t0 + 8]       = __float2half(acc[mt][nt][2]);
                vb[(size_t)(d + 1) * SEQ + t0 + 8] = __float2half(acc[mt][nt][3]);
            }
        }
    }
}

// ---------------------------------------------------------------------------
// Pre-passes
// ---------------------------------------------------------------------------
__global__ void __launch_bounds__(256) cvt_fp16_kernel(
    const float4* __restrict__ in, uint2* __restrict__ out, int n8)
{
    int i = blockIdx.x * blockDim.x + threadIdx.x;
    if (i < n8) {
        float4 a = in[2 * i], b = in[2 * i + 1];
        uint2 o;
        o.x = pack_h2(a.x, a.y);  o.y = pack_h2(a.z, a.w);
        uint2 o2;
        o2.x = pack_h2(b.x, b.y); o2.y = pack_h2(b.z, b.w);
        out[2 * i] = o; out[2 * i + 1] = o2;
    }
}

// W[K][N] -> Wt[N][K] fp16
__global__ void __launch_bounds__(256) transpose_fp16_kernel(
    const float* __restrict__ W, __half* __restrict__ Wt, int K, int N)
{
    __shared__ float t[32][33];
    const int n0 = blockIdx.x * 32, k0 = blockIdx.y * 32;
    const int tx = threadIdx.x, ty = threadIdx.y;   // 32 x 8
#pragma unroll
    for (int i = 0; i < 4; ++i)
        t[ty + i * 8][tx] = W[(size_t)(k0 + ty + i * 8) * N + n0 + tx];
    __syncthreads();
#pragma unroll
    for (int i = 0; i < 4; ++i)
        Wt[(size_t)(n0 + ty + i * 8) * K + k0 + tx] = __float2half(t[tx][ty + i * 8]);
}

// ---------------------------------------------------------------------------
// Tensor-core causal flash attention (tf32 QK^T + fp16 PV, ldmatrix frags).
// Grid (16 q-tiles x 128, 16 heads, 4 batch), 256 threads = 8 warps.
// Epilogue now writes fp16 (input to fp16 GEMM2).
// ---------------------------------------------------------------------------
#define KSTR 68
#define KBUF (64 * KSTR)              // floats per K buffer
#define VSTR 72
#define VBUF (64 * VSTR)              // halves per V buffer
#define VOFF (2 * KBUF * 4)           // byte offset of V region
#define ATTN_SMEM (VOFF + 2 * VBUF * 2)   // 53248 bytes

__global__ void __launch_bounds__(256) attn_mma_kernel(
    const float* __restrict__ qkv, const __half* __restrict__ vh,
    __half* __restrict__ out)
{
    extern __shared__ float sm[];

    const int tid = threadIdx.x, wq = tid >> 5, lane = tid & 31;
    const int q = lane >> 2, cc = lane & 3;
    const int rt = blockIdx.x, h = blockIdx.y, b = blockIdx.z;
    const int qb = rt * 128;
    const int nkt = 2 * rt + 2;
    const float* base = qkv + (size_t)b * SEQ * QKVCOLS;
    const __half* vbase = vh + ((size_t)(b * NHEADS + h) * DHEAD) * SEQ;
    const uint32_t smb = smem_u32(sm);

    const int brow = (lane & 7) + (lane >> 4) * 8;
    const int bcol = ((lane >> 3) & 1) * 4;     // floats
    const int vrow = (lane & 7) + (lane >> 4) * 8;
    const int vcol = ((lane >> 3) & 1) * 8;     // halves

    uint32_t aq[8][4];
    {
        const int r0 = qb + wq * 16 + q;
#pragma unroll
        for (int ks = 0; ks < 8; ++ks)
#pragma unroll
            for (int e = 0; e < 4; ++e) {
                const int row = r0 + (e & 1) * 8;
                const int col = h * DHEAD + 8 * ks + cc + (e >> 1) * 4;
                aq[ks][e] = __float_as_uint(
                    0.125f * base[(size_t)row * QKVCOLS + col]);
            }
    }

    float oacc[8][4];
#pragma unroll
    for (int nt = 0; nt < 8; ++nt)
#pragma unroll
        for (int e = 0; e < 4; ++e) oacc[nt][e] = 0.0f;
    float m0 = -INFINITY, m1 = -INFINITY, l0 = 0.0f, l1 = 0.0f;

    auto cptile = [&](int kt, int bufsel) {
        const float* kS = base + (size_t)(kt * 64) * QKVCOLS + DMODEL + h * DHEAD;
        const uint32_t kD = smb + (uint32_t)bufsel * KBUF * 4;
#pragma unroll
        for (int i = 0; i < 4; ++i) {
            const int ch  = tid + i * 256;
            const int row = ch >> 4;
            const int c4  = (ch & 15) << 2;
            CP_ASYNC16(kD + (row * KSTR + c4) * 4, kS + (size_t)row * QKVCOLS + c4);
        }
        const __half* vS = vbase + kt * 64;
        const uint32_t vD = smb + VOFF + (uint32_t)bufsel * VBUF * 2;
#pragma unroll
        for (int i = 0; i < 2; ++i) {
            const int ch = tid + i * 256;
            const int d  = ch >> 3;
            const int c8 = (ch & 7) << 3;
            CP_ASYNC16(vD + (d * VSTR + c8) * 2, vS + (size_t)d * SEQ + c8);
        }
        CP_COMMIT();
    };

    cptile(0, 0);

    for (int kt = 0; kt < nkt; ++kt) {
        const int buf = kt & 1;
        if (kt + 1 < nkt) { cptile(kt + 1, (kt + 1) & 1); CP_WAIT_1(); }
        else              { CP_WAIT_0(); }
        __syncthreads();

        const uint32_t kAddr = smb + (uint32_t)buf * KBUF * 4
                             + (brow * KSTR + bcol) * 4;
        const uint32_t vAddr = smb + VOFF + (uint32_t)buf * VBUF * 2
                             + (vrow * VSTR + vcol) * 2;

        // ---- S = (Q/8) K^T ----
        float sacc[8][4];
#pragma unroll
        for (int hh = 0; hh < 4; ++hh) {
            sacc[2*hh][0] = sacc[2*hh][1] = sacc[2*hh][2] = sacc[2*hh][3] = 0.0f;
            sacc[2*hh+1][0] = sacc[2*hh+1][1] = sacc[2*hh+1][2] = sacc[2*hh+1][3] = 0.0f;
#pragma unroll
            for (int ks = 0; ks < 8; ++ks) {
                uint32_t kb[4];
                ldm_x4(kb, kAddr + (hh * 16 * KSTR + ks * 8) * 4);
                mma1688(sacc[2 * hh],     aq[ks], &kb[0]);
                mma1688(sacc[2 * hh + 1], aq[ks], &kb[2]);
            }
        }

        if (kt * 64 + 63 > qb + wq * 16) {
            const int r0g = qb + wq * 16 + q, r1g = r0g + 8;
#pragma unroll
            for (int nt = 0; nt < 8; ++nt) {
                const int c0g = kt * 64 + 8 * nt + 2 * cc;
                if (c0g     > r0g) sacc[nt][0] = -INFINITY;
                if (c0g + 1 > r0g) sacc[nt][1] = -INFINITY;
                if (c0g     > r1g) sacc[nt][2] = -INFINITY;
                if (c0g + 1 > r1g) sacc[nt][3] = -INFINITY;
            }
        }

        float cm0 = -INFINITY, cm1 = -INFINITY;
#pragma unroll
        for (int nt = 0; nt < 8; ++nt) {
            cm0 = fmaxf(cm0, fmaxf(sacc[nt][0], sacc[nt][1]));
            cm1 = fmaxf(cm1, fmaxf(sacc[nt][2], sacc[nt][3]));
        }
        cm0 = fmaxf(cm0, __shfl_xor_sync(0xffffffffu, cm0, 1));
        cm0 = fmaxf(cm0, __shfl_xor_sync(0xffffffffu, cm0, 2));
        cm1 = fmaxf(cm1, __shfl_xor_sync(0xffffffffu, cm1, 1));
        cm1 = fmaxf(cm1, __shfl_xor_sync(0xffffffffu, cm1, 2));

        const float mn0 = fmaxf(m0, cm0), mn1 = fmaxf(m1, cm1);
        const float corr0 = __expf(m0 - mn0), corr1 = __expf(m1 - mn1);

        uint32_t ph[8][2];
        float ps0 = 0.0f, ps1 = 0.0f;
#pragma unroll
        for (int nt = 0; nt < 8; ++nt) {
            const float pp0 = __expf(sacc[nt][0] - mn0);
            const float pp1 = __expf(sacc[nt][1] - mn0);
            const float pp2 = __expf(sacc[nt][2] - mn1);
            const float pp3 = __expf(sacc[nt][3] - mn1);
            ps0 += pp0 + pp1; ps1 += pp2 + pp3;
            ph[nt][0] = pack_h2(pp0, pp1);
            ph[nt][1] = pack_h2(pp2, pp3);
            oacc[nt][0] *= corr0; oacc[nt][1] *= corr0;
            oacc[nt][2] *= corr1; oacc[nt][3] *= corr1;
        }
        l0 = l0 * corr0 + ps0;
        l1 = l1 * corr1 + ps1;
        m0 = mn0; m1 = mn1;

#pragma unroll
        for (int g = 0; g < 4; ++g) {
            uint32_t ap[4] = { ph[2 * g][0], ph[2 * g][1],
                               ph[2 * g + 1][0], ph[2 * g + 1][1] };
#pragma unroll
            for (int hh = 0; hh < 4; ++hh) {
                uint32_t vb4[4];
                ldm_x4(vb4, vAddr + (hh * 16 * VSTR + g * 16) * 2);
                mma16816h(oacc[2 * hh],     ap, vb4[0], vb4[1]);
                mma16816h(oacc[2 * hh + 1], ap, vb4[2], vb4[3]);
            }
        }
        __syncthreads();
    }

    // ---- epilogue: fp16 output (GEMM2 consumes fp16) ----
    l0 += __shfl_xor_sync(0xffffffffu, l0, 1);
    l0 += __shfl_xor_sync(0xffffffffu, l0, 2);
    l1 += __shfl_xor_sync(0xffffffffu, l1, 1);
    l1 += __shfl_xor_sync(0xffffffffu, l1, 2);
    const float inv0 = 1.0f / l0, inv1 = 1.0f / l1;

    __half* ob = out + (size_t)(b * SEQ + qb + wq * 16 + q) * DMODEL + h * DHEAD;
#pragma unroll
    for (int nt = 0; nt < 8; ++nt) {
        *reinterpret_cast<uint32_t*>(&ob[8 * nt + 2 * cc]) =
            pack_h2(oacc[nt][0] * inv0, oacc[nt][1] * inv0);
        *reinterpret_cast<uint32_t*>(&ob[(size_t)8 * DMODEL + 8 * nt + 2 * cc]) =
            pack_h2(oacc[nt][2] * inv1, oacc[nt][3] * inv1);
    }
}

// ---------------------------------------------------------------------------
extern "C" void kernel_launch(void* const* d_in, const int* in_sizes, int n_in,
                              void* d_out, int out_size)
{
    const float* x     = (const float*)d_in[0];
    const float* W_qkv = (const float*)d_in[1];
    const float* W_out = (const float*)d_in[2];
    float* out = (float*)d_out;

    float* qkv;
    __half *xh, *attnh, *wqkvTh, *woutTh, *vh;
    cudaGetSymbolAddress((void**)&xh,     g_xh);
    cudaGetSymbolAddress((void**)&qkv,    g_qkv);
    cudaGetSymbolAddress((void**)&attnh,  g_attnh);
    cudaGetSymbolAddress((void**)&wqkvTh, g_wqkvTh);
    cudaGetSymbolAddress((void**)&woutTh, g_woutTh);
    cudaGetSymbolAddress((void**)&vh,     g_vh);

    cudaFuncSetAttribute(gemm_fp16_kernel,
                         cudaFuncAttributeMaxDynamicSharedMemorySize, GEMM_SMEM);
    cudaFuncSetAttribute(attn_mma_kernel,
                         cudaFuncAttributeMaxDynamicSharedMemorySize, ATTN_SMEM);

    // Pre-passes: fp16 conversion + fp16 weight transposes
    const int n8 = MROWS * DMODEL / 8;
    cvt_fp16_kernel<<<n8 / 256, 256>>>((const float4*)x, (uint2*)xh, n8);
    transpose_fp16_kernel<<<dim3(QKVCOLS / 32, DMODEL / 32), dim3(32, 8)>>>(
        W_qkv, wqkvTh, DMODEL, QKVCOLS);
    transpose_fp16_kernel<<<dim3(DMODEL / 32, DMODEL / 32), dim3(32, 8)>>>(
        W_out, woutTh, DMODEL, DMODEL);

    // 1) QKV projection (fp16 MMA, f32 accum): tf32 Q/K + fp16 V^T
    gemm_fp16_kernel<<<dim3(QKVCOLS / 128, MROWS / 128), 256, GEMM_SMEM>>>(
        xh, wqkvTh, qkv, vh, MROWS, QKVCOLS, DMODEL, 1);

    // 2) Flash attention (tf32 QK^T, fp16 PV) -> fp16 out
    attn_mma_kernel<<<dim3(SEQ / 128, NHEADS, BSZ), 256, ATTN_SMEM>>>(qkv, vh, attnh);

    // 3) Output projection (fp16 MMA, f32 accum) -> f32 result
    gemm_fp16_kernel<<<dim3(DMODEL / 128, MROWS / 128), 256, GEMM_SMEM>>>(
        attnh, woutTh, out, vh, MROWS, DMODEL, DMODEL, 0);
}

// round 9
// speedup vs baseline: 9.5423x; 1.2003x over previous
#include <cuda_runtime.h>
#include <cuda_fp16.h>
#include <cstdint>
#include <math.h>

// Problem constants
#define BSZ 4
#define SEQ 2048
#define DMODEL 1024
#define NHEADS 16
#define DHEAD 64
#define QKVCOLS (3 * DMODEL)          // 3072
#define MROWS (BSZ * SEQ)             // 8192

// Scratch (device globals)
__device__ __half g_xh    [(size_t)MROWS * DMODEL];    // x, fp16
__device__ __half g_qkh   [(size_t)MROWS * 2 * DMODEL];// Q,K fp16 [row][0..2047]
__device__ __half g_attnh [(size_t)MROWS * DMODEL];    // attn out, fp16
__device__ __half g_wqkvTh[(size_t)QKVCOLS * DMODEL];  // W_qkv^T, fp16
__device__ __half g_woutTh[(size_t)DMODEL * DMODEL];   // W_out^T, fp16
__device__ __half g_vh    [(size_t)BSZ * NHEADS * DHEAD * SEQ]; // V^T fp16 [b][h][d][t]

// ---------------------------------------------------------------------------
// Helpers
// ---------------------------------------------------------------------------
__device__ __forceinline__ uint32_t smem_u32(const void* p) {
    uint32_t a;
    asm("{ .reg .u64 t; cvta.to.shared.u64 t, %1; cvt.u32.u64 %0, t; }"
        : "=r"(a) : "l"(p));
    return a;
}
__device__ __forceinline__ uint32_t pack_h2(float a, float b) {
    __half2 h = __floats2half2_rn(a, b);
    return *reinterpret_cast<uint32_t*>(&h);
}

#define CP_ASYNC16(dst_u32, src_ptr) \
    asm volatile("cp.async.ca.shared.global [%0], [%1], 16;" \
                 :: "r"(dst_u32), "l"(src_ptr) : "memory")
#define CP_COMMIT() asm volatile("cp.async.commit_group;" ::: "memory")
#define CP_WAIT_1() asm volatile("cp.async.wait_group 1;" ::: "memory")
#define CP_WAIT_0() asm volatile("cp.async.wait_group 0;" ::: "memory")

__device__ __forceinline__ void ldm_x4(uint32_t* r, uint32_t addr) {
    asm volatile("ldmatrix.sync.aligned.m8n8.x4.shared.b16 {%0,%1,%2,%3}, [%4];"
        : "=r"(r[0]), "=r"(r[1]), "=r"(r[2]), "=r"(r[3]) : "r"(addr));
}

// fp16 m16n8k16, f32 accumulate
__device__ __forceinline__ void mma16816h(float* d, const uint32_t* a,
                                          uint32_t b0, uint32_t b1) {
    asm volatile(
        "mma.sync.aligned.m16n8k16.row.col.f32.f16.f16.f32 "
        "{%0,%1,%2,%3}, {%4,%5,%6,%7}, {%8,%9}, {%0,%1,%2,%3};"
        : "+f"(d[0]), "+f"(d[1]), "+f"(d[2]), "+f"(d[3])
        : "r"(a[0]), "r"(a[1]), "r"(a[2]), "r"(a[3]), "r"(b0), "r"(b1));
}

// ---------------------------------------------------------------------------
// fp16 GEMM: C[M,N] = A[M,K] * Bt[N,K]^T, f32 accumulate.
// 128x128 CTA tiles, BK=64, cp.async double buffer, 8 warps 64x32 each.
// mode 0: f32 out (final). mode 1: QKV (cols<2048 -> fp16 Q/K into qkh;
// >=2048 -> fp16 V^T into vh).
// ---------------------------------------------------------------------------
#define GSTR 72
#define GBUF (128 * GSTR * 2)         // bytes per A (or B) buffer = 18432
#define GEMM_SMEM (4 * GBUF)          // 73728

__global__ void __launch_bounds__(256) gemm_fp16_kernel(
    const __half* __restrict__ A, const __half* __restrict__ Bt,
    float* __restrict__ C, __half* __restrict__ qkh, __half* __restrict__ vh,
    int M, int N, int K, int mode)
{
    extern __shared__ char smem[];
    const int tid = threadIdx.x, wid = tid >> 5, lane = tid & 31;
    const int rowBase = blockIdx.y << 7, colBase = blockIdx.x << 7;
    const uint32_t sb = smem_u32(smem);

    const int wr = wid >> 2, wc = wid & 3;
    const int q = lane >> 2, cc = lane & 3;

    const int ar = (lane & 7) + ((lane >> 3) & 1) * 8;  // A: {r,r+8} x {k,k+8}
    const int ac = (lane >> 4) * 8;
    const int br = (lane & 7) + (lane >> 4) * 8;        // B: {n,n+8} x {k,k+8}
    const int bc = ((lane >> 3) & 1) * 8;

    float acc[4][4][4];
#pragma unroll
    for (int a = 0; a < 4; ++a)
#pragma unroll
        for (int b = 0; b < 4; ++b)
#pragma unroll
            for (int r = 0; r < 4; ++r) acc[a][b][r] = 0.0f;

    const int nchunks = K >> 6;

    auto load_tile = [&](int c, int buf) {
        const int k0 = c << 6;
#pragma unroll
        for (int i = 0; i < 4; ++i) {
            const int f   = tid + i * 256;
            const int row = f >> 3;
            const int c8  = (f & 7) << 3;
            CP_ASYNC16(sb + buf * GBUF + (row * GSTR + c8) * 2,
                       &A[(size_t)(rowBase + row) * K + k0 + c8]);
            CP_ASYNC16(sb + 2 * GBUF + buf * GBUF + (row * GSTR + c8) * 2,
                       &Bt[(size_t)(colBase + row) * K + k0 + c8]);
        }
        CP_COMMIT();
    };

    load_tile(0, 0);

    for (int c = 0; c < nchunks; ++c) {
        const int buf = c & 1;
        if (c + 1 < nchunks) { load_tile(c + 1, (c + 1) & 1); CP_WAIT_1(); }
        else                 { CP_WAIT_0(); }
        __syncthreads();

        const uint32_t aAddr = sb + buf * GBUF + ((wr * 64 + ar) * GSTR + ac) * 2;
        const uint32_t bAddr = sb + 2 * GBUF + buf * GBUF
                             + ((wc * 32 + br) * GSTR + bc) * 2;

#pragma unroll
        for (int ks = 0; ks < 4; ++ks) {
            uint32_t bfr[2][4];
#pragma unroll
            for (int nh = 0; nh < 2; ++nh)
                ldm_x4(bfr[nh], bAddr + (nh * 16 * GSTR + ks * 16) * 2);
#pragma unroll
            for (int mt = 0; mt < 4; ++mt) {
                uint32_t af[4];
                ldm_x4(af, aAddr + (mt * 16 * GSTR + ks * 16) * 2);
#pragma unroll
                for (int nh = 0; nh < 2; ++nh) {
                    mma16816h(acc[mt][2 * nh],     af, bfr[nh][0], bfr[nh][1]);
                    mma16816h(acc[mt][2 * nh + 1], af, bfr[nh][2], bfr[nh][3]);
                }
            }
        }
        __syncthreads();
    }

    // Epilogue
#pragma unroll
    for (int mt = 0; mt < 4; ++mt) {
        const int row0 = rowBase + wr * 64 + mt * 16 + q;
#pragma unroll
        for (int nt = 0; nt < 4; ++nt) {
            const int grp = colBase + wc * 32 + nt * 8;
            if (mode == 0) {
                *reinterpret_cast<float2*>(&C[(size_t)row0 * N + grp + 2 * cc]) =
                    make_float2(acc[mt][nt][0], acc[mt][nt][1]);
                *reinterpret_cast<float2*>(&C[(size_t)(row0 + 8) * N + grp + 2 * cc]) =
                    make_float2(acc[mt][nt][2], acc[mt][nt][3]);
            } else if (grp < 2048) {
                // Q/K region -> fp16 qkh [row][0..2047]
                *reinterpret_cast<uint32_t*>(
                    &qkh[(size_t)row0 * 2048 + grp + 2 * cc]) =
                    pack_h2(acc[mt][nt][0], acc[mt][nt][1]);
                *reinterpret_cast<uint32_t*>(
                    &qkh[(size_t)(row0 + 8) * 2048 + grp + 2 * cc]) =
                    pack_h2(acc[mt][nt][2], acc[mt][nt][3]);
            } else {
                // V region -> fp16 V^T [b][h][d][t]
                const int dg = grp - 2048 + 2 * cc;
                const int h = dg >> 6, d = dg & 63;
                const int b0r = row0 >> 11, t0 = row0 & 2047;
                __half* vb = vh + ((size_t)(b0r * NHEADS + h) * DHEAD) * SEQ;
                vb[(size_t)d * SEQ + t0]           = __float2half(acc[mt][nt][0]);
                vb[(size_t)(d + 1) * SEQ + t0]     = __float2half(acc[mt][nt][1]);
                vb[(size_t)d * SEQ + t0 + 8]       = __float2half(acc[mt][nt][2]);
                vb[(size_t)(d + 1) * SEQ + t0 + 8] = __float2half(acc[mt][nt][3]);
            }
        }
    }
}

// ---------------------------------------------------------------------------
// Pre-passes
// ---------------------------------------------------------------------------
__global__ void __launch_bounds__(256) cvt_fp16_kernel(
    const float4* __restrict__ in, uint2* __restrict__ out, int n8)
{
    int i = blockIdx.x * blockDim.x + threadIdx.x;
    if (i < n8) {
        float4 a = in[2 * i], b = in[2 * i + 1];
        uint2 o, o2;
        o.x = pack_h2(a.x, a.y);  o.y = pack_h2(a.z, a.w);
        o2.x = pack_h2(b.x, b.y); o2.y = pack_h2(b.z, b.w);
        out[2 * i] = o; out[2 * i + 1] = o2;
    }
}

__global__ void __launch_bounds__(256) transpose_fp16_kernel(
    const float* __restrict__ W, __half* __restrict__ Wt, int K, int N)
{
    __shared__ float t[32][33];
    const int n0 = blockIdx.x * 32, k0 = blockIdx.y * 32;
    const int tx = threadIdx.x, ty = threadIdx.y;   // 32 x 8
#pragma unroll
    for (int i = 0; i < 4; ++i)
        t[ty + i * 8][tx] = W[(size_t)(k0 + ty + i * 8) * N + n0 + tx];
    __syncthreads();
#pragma unroll
    for (int i = 0; i < 4; ++i)
        Wt[(size_t)(n0 + ty + i * 8) * K + k0 + tx] = __float2half(t[tx][ty + i * 8]);
}

// ---------------------------------------------------------------------------
// Tensor-core causal flash attention — all fp16 MMAs (QK^T and PV), f32
// softmax/accum. Grid (16 q-tiles x 128, 16 heads, 4 batch), 8 warps.
// K tiles [t][d] and V^T tiles [d][t], both 64x64 fp16 rows stride 72.
// ---------------------------------------------------------------------------
#define STR 72
#define TBUF (64 * STR * 2)           // bytes per 64x64 fp16 buffer = 9216
#define ATTN_SMEM (4 * TBUF)          // 36864

__global__ void __launch_bounds__(256) attn_mma_kernel(
    const __half* __restrict__ qkh, const __half* __restrict__ vh,
    __half* __restrict__ out)
{
    extern __shared__ char smc[];

    const int tid = threadIdx.x, wq = tid >> 5, lane = tid & 31;
    const int q = lane >> 2, cc = lane & 3;
    const int rt = blockIdx.x, h = blockIdx.y, b = blockIdx.z;
    const int qb = rt * 128;
    const int nkt = 2 * rt + 2;
    const __half* base = qkh + (size_t)b * SEQ * 2048;
    const __half* vbase = vh + ((size_t)(b * NHEADS + h) * DHEAD) * SEQ;
    const uint32_t smb = smem_u32(smc);

    // ldmatrix b-frag lane offsets (shared by K and V)
    const int brow = (lane & 7) + (lane >> 4) * 8;
    const int bcol = ((lane >> 3) & 1) * 8;     // halves

    // Resident Q a-frags (fp16, scaled by 1/8 exactly)
    uint32_t aq[4][4];
    {
        const int r0 = qb + wq * 16 + q;
        const __half2 s8 = __half2half2(__float2half(0.125f));
#pragma unroll
        for (int ks = 0; ks < 4; ++ks)
#pragma unroll
            for (int e = 0; e < 4; ++e) {
                const int row = r0 + (e & 1) * 8;
                const int col = h * DHEAD + 16 * ks + 2 * cc + (e >> 1) * 8;
                __half2 v = *reinterpret_cast<const __half2*>(
                    &base[(size_t)row * 2048 + col]);
                v = __hmul2(v, s8);
                aq[ks][e] = *reinterpret_cast<uint32_t*>(&v);
            }
    }

    float oacc[8][4];
#pragma unroll
    for (int nt = 0; nt < 8; ++nt)
#pragma unroll
        for (int e = 0; e < 4; ++e) oacc[nt][e] = 0.0f;
    float m0 = -INFINITY, m1 = -INFINITY, l0 = 0.0f, l1 = 0.0f;

    auto cptile = [&](int kt, int bufsel) {
        // K: 64 t-rows x 64 halves
        const __half* kS = base + (size_t)(kt * 64) * 2048 + 1024 + h * DHEAD;
        const uint32_t kD = smb + (uint32_t)bufsel * TBUF;
#pragma unroll
        for (int i = 0; i < 2; ++i) {
            const int ch = tid + i * 256;
            const int row = ch >> 3;
            const int c8  = (ch & 7) << 3;
            CP_ASYNC16(kD + (row * STR + c8) * 2, kS + (size_t)row * 2048 + c8);
        }
        // V^T: 64 d-rows x 64 halves
        const __half* vS = vbase + kt * 64;
        const uint32_t vD = smb + 2 * TBUF + (uint32_t)bufsel * TBUF;
#pragma unroll
        for (int i = 0; i < 2; ++i) {
            const int ch = tid + i * 256;
            const int d  = ch >> 3;
            const int c8 = (ch & 7) << 3;
            CP_ASYNC16(vD + (d * STR + c8) * 2, vS + (size_t)d * SEQ + c8);
        }
        CP_COMMIT();
    };

    cptile(0, 0);

    for (int kt = 0; kt < nkt; ++kt) {
        const int buf = kt & 1;
        if (kt + 1 < nkt) { cptile(kt + 1, (kt + 1) & 1); CP_WAIT_1(); }
        else              { CP_WAIT_0(); }
        __syncthreads();

        const uint32_t kAddr = smb + (uint32_t)buf * TBUF + (brow * STR + bcol) * 2;
        const uint32_t vAddr = smb + 2 * TBUF + (uint32_t)buf * TBUF
                             + (brow * STR + bcol) * 2;

        // ---- S = (Q/8) K^T (fp16 m16n8k16) ----
        float sacc[8][4];
#pragma unroll
        for (int hh = 0; hh < 4; ++hh) {
            sacc[2*hh][0] = sacc[2*hh][1] = sacc[2*hh][2] = sacc[2*hh][3] = 0.0f;
            sacc[2*hh+1][0] = sacc[2*hh+1][1] = sacc[2*hh+1][2] = sacc[2*hh+1][3] = 0.0f;
#pragma unroll
            for (int ks = 0; ks < 4; ++ks) {
                uint32_t kb[4];
                ldm_x4(kb, kAddr + (hh * 16 * STR + ks * 16) * 2);
                mma16816h(sacc[2 * hh],     aq[ks], kb[0], kb[1]);
                mma16816h(sacc[2 * hh + 1], aq[ks], kb[2], kb[3]);
            }
        }

        // ---- causal mask ----
        if (kt * 64 + 63 > qb + wq * 16) {
            const int r0g = qb + wq * 16 + q, r1g = r0g + 8;
#pragma unroll
            for (int nt = 0; nt < 8; ++nt) {
                const int c0g = kt * 64 + 8 * nt + 2 * cc;
                if (c0g     > r0g) sacc[nt][0] = -INFINITY;
                if (c0g + 1 > r0g) sacc[nt][1] = -INFINITY;
                if (c0g     > r1g) sacc[nt][2] = -INFINITY;
                if (c0g + 1 > r1g) sacc[nt][3] = -INFINITY;
            }
        }

        // ---- online softmax; P -> fp16 a-frags in registers ----
        float cm0 = -INFINITY, cm1 = -INFINITY;
#pragma unroll
        for (int nt = 0; nt < 8; ++nt) {
            cm0 = fmaxf(cm0, fmaxf(sacc[nt][0], sacc[nt][1]));
            cm1 = fmaxf(cm1, fmaxf(sacc[nt][2], sacc[nt][3]));
        }
        cm0 = fmaxf(cm0, __shfl_xor_sync(0xffffffffu, cm0, 1));
        cm0 = fmaxf(cm0, __shfl_xor_sync(0xffffffffu, cm0, 2));
        cm1 = fmaxf(cm1, __shfl_xor_sync(0xffffffffu, cm1, 1));
        cm1 = fmaxf(cm1, __shfl_xor_sync(0xffffffffu, cm1, 2));

        const float mn0 = fmaxf(m0, cm0), mn1 = fmaxf(m1, cm1);
        const float corr0 = __expf(m0 - mn0), corr1 = __expf(m1 - mn1);

        uint32_t ph[8][2];
        float ps0 = 0.0f, ps1 = 0.0f;
#pragma unroll
        for (int nt = 0; nt < 8; ++nt) {
            const float pp0 = __expf(sacc[nt][0] - mn0);
            const float pp1 = __expf(sacc[nt][1] - mn0);
            const float pp2 = __expf(sacc[nt][2] - mn1);
            const float pp3 = __expf(sacc[nt][3] - mn1);
            ps0 += pp0 + pp1; ps1 += pp2 + pp3;
            ph[nt][0] = pack_h2(pp0, pp1);
            ph[nt][1] = pack_h2(pp2, pp3);
            oacc[nt][0] *= corr0; oacc[nt][1] *= corr0;
            oacc[nt][2] *= corr1; oacc[nt][3] *= corr1;
        }
        l0 = l0 * corr0 + ps0;
        l1 = l1 * corr1 + ps1;
        m0 = mn0; m1 = mn1;

        // ---- O += P V (fp16 m16n8k16) ----
#pragma unroll
        for (int g = 0; g < 4; ++g) {
            uint32_t ap[4] = { ph[2 * g][0], ph[2 * g][1],
                               ph[2 * g + 1][0], ph[2 * g + 1][1] };
#pragma unroll
            for (int hh = 0; hh < 4; ++hh) {
                uint32_t vb4[4];
                ldm_x4(vb4, vAddr + (hh * 16 * STR + g * 16) * 2);
                mma16816h(oacc[2 * hh],     ap, vb4[0], vb4[1]);
                mma16816h(oacc[2 * hh + 1], ap, vb4[2], vb4[3]);
            }
        }
        __syncthreads();
    }

    // ---- epilogue: fp16 output (GEMM2 consumes fp16) ----
    l0 += __shfl_xor_sync(0xffffffffu, l0, 1);
    l0 += __shfl_xor_sync(0xffffffffu, l0, 2);
    l1 += __shfl_xor_sync(0xffffffffu, l1, 1);
    l1 += __shfl_xor_sync(0xffffffffu, l1, 2);
    const float inv0 = 1.0f / l0, inv1 = 1.0f / l1;

    __half* ob = out + (size_t)(b * SEQ + qb + wq * 16 + q) * DMODEL + h * DHEAD;
#pragma unroll
    for (int nt = 0; nt < 8; ++nt) {
        *reinterpret_cast<uint32_t*>(&ob[8 * nt + 2 * cc]) =
            pack_h2(oacc[nt][0] * inv0, oacc[nt][1] * inv0);
        *reinterpret_cast<uint32_t*>(&ob[(size_t)8 * DMODEL + 8 * nt + 2 * cc]) =
            pack_h2(oacc[nt][2] * inv1, oacc[nt][3] * inv1);
    }
}

// ---------------------------------------------------------------------------
extern "C" void kernel_launch(void* const* d_in, const int* in_sizes, int n_in,
                              void* d_out, int out_size)
{
    const float* x     = (const float*)d_in[0];
    const float* W_qkv = (const float*)d_in[1];
    const float* W_out = (const float*)d_in[2];
    float* out = (float*)d_out;

    __half *xh, *qkh, *attnh, *wqkvTh, *woutTh, *vh;
    cudaGetSymbolAddress((void**)&xh,     g_xh);
    cudaGetSymbolAddress((void**)&qkh,    g_qkh);
    cudaGetSymbolAddress((void**)&attnh,  g_attnh);
    cudaGetSymbolAddress((void**)&wqkvTh, g_wqkvTh);
    cudaGetSymbolAddress((void**)&woutTh, g_woutTh);
    cudaGetSymbolAddress((void**)&vh,     g_vh);

    cudaFuncSetAttribute(gemm_fp16_kernel,
                         cudaFuncAttributeMaxDynamicSharedMemorySize, GEMM_SMEM);
    cudaFuncSetAttribute(attn_mma_kernel,
                         cudaFuncAttributeMaxDynamicSharedMemorySize, ATTN_SMEM);

    // Pre-passes
    const int n8 = MROWS * DMODEL / 8;
    cvt_fp16_kernel<<<n8 / 256, 256>>>((const float4*)x, (uint2*)xh, n8);
    transpose_fp16_kernel<<<dim3(QKVCOLS / 32, DMODEL / 32), dim3(32, 8)>>>(
        W_qkv, wqkvTh, DMODEL, QKVCOLS);
    transpose_fp16_kernel<<<dim3(DMODEL / 32, DMODEL / 32), dim3(32, 8)>>>(
        W_out, woutTh, DMODEL, DMODEL);

    // 1) QKV projection (fp16 MMA): fp16 Q/K + fp16 V^T
    gemm_fp16_kernel<<<dim3(QKVCOLS / 128, MROWS / 128), 256, GEMM_SMEM>>>(
        xh, wqkvTh, nullptr, qkh, vh, MROWS, QKVCOLS, DMODEL, 1);

    // 2) Flash attention (fp16 QK^T + fp16 PV) -> fp16 out
    attn_mma_kernel<<<dim3(SEQ / 128, NHEADS, BSZ), 256, ATTN_SMEM>>>(qkh, vh, attnh);

    // 3) Output projection (fp16 MMA) -> f32 result
    gemm_fp16_kernel<<<dim3(DMODEL / 128, MROWS / 128), 256, GEMM_SMEM>>>(
        attnh, woutTh, out, nullptr, nullptr, MROWS, DMODEL, DMODEL, 0);
}